// round 1
// baseline (speedup 1.0000x reference)
#include <cuda_runtime.h>

#define NN   150000
#define EE   1200000
#define CC   64
#define ACTD 6
#define BB   25000
#define HHH  32
#define GLB  256
#define GOUT 10
#define KIN  384   // C*ACT

// ---------------- static device scratch (no allocs allowed) ----------------
__device__ __align__(16) float g_h[NN * CC];     // state @ convW^T
__device__ __align__(16) float g_agg[NN * CC];   // GCN aggregation
__device__ float g_deg[NN];
__device__ float g_dinv[NN];
__device__ int   g_src[EE];
__device__ int   g_dst[EE];
__device__ float g_gW1t[KIN * GLB];              // gW1 transposed [k][j]
__device__ float g_xg[BB * GOUT];
__device__ float g_conc[NN];
__device__ float g_sum;

// ---------------- helpers ----------------
__device__ __forceinline__ float leakyf(float x) { return x > 0.f ? x : 0.01f * x; }
__device__ __forceinline__ float softplusf(float x) {
    // stable: max(x,0) + log1p(exp(-|x|))
    return fmaxf(x, 0.f) + log1pf(expf(-fabsf(x)));
}

__device__ __forceinline__ unsigned long long pk2(float x, float y) {
    unsigned long long r;
    asm("mov.b64 %0, {%1, %2};" : "=l"(r) : "f"(x), "f"(y));
    return r;
}
__device__ __forceinline__ void fma2(unsigned long long& d, unsigned long long a,
                                     unsigned long long b) {
    asm("fma.rn.f32x2 %0, %1, %2, %3;" : "=l"(d) : "l"(a), "l"(b), "l"(d));
}
__device__ __forceinline__ float2 up2(unsigned long long v) {
    float lo, hi;
    asm("mov.b64 {%0, %1}, %2;" : "=f"(lo), "=f"(hi) : "l"(v));
    return make_float2(lo, hi);
}

// ---------------- kernels ----------------
__global__ void k_zero() {
    int i = blockIdx.x * 256 + threadIdx.x;
    if (i < NN) g_deg[i] = 0.f;
    if (i == 0) g_sum = 0.f;
}

// Convert edge_index (int64 or int32, auto-detected) to int32 src/dst + degree count
__global__ void k_edges(const void* __restrict__ eidx) {
    int e = blockIdx.x * 256 + threadIdx.x;
    if (e >= EE) return;
    const long long* p64 = (const long long*)eidx;
    bool is64 = true;
#pragma unroll
    for (int t = 0; t < 8; t++) {
        unsigned long long v = (unsigned long long)p64[t];
        if (v >= (unsigned long long)NN) is64 = false;
    }
    int s, d;
    if (is64) {
        s = (int)p64[e];
        d = (int)p64[EE + e];
    } else {
        const int* p32 = (const int*)eidx;
        s = p32[e];
        d = p32[EE + e];
    }
    g_src[e] = s;
    g_dst[e] = d;
    atomicAdd(&g_deg[d], 1.0f);
}

__global__ void k_dinv() {
    int i = blockIdx.x * 256 + threadIdx.x;
    if (i < NN) g_dinv[i] = rsqrtf(g_deg[i] + 1.0f);
}

// h = state @ convW^T ; agg = h * dinv^2 (self-loop init). 64 rows per block.
__global__ void k_conv(const float* __restrict__ state, const float* __restrict__ convW) {
    __shared__ float sW[64 * 65];   // [k][o] padded
    __shared__ float sX[64 * 34];   // [k][r] 32 rows padded to 34
    int tid = threadIdx.x;
    for (int idx = tid; idx < 4096; idx += 256) {
        int o = idx >> 6, k = idx & 63;
        sW[k * 65 + o] = convW[idx];
    }
    int o = tid & 63, quad = tid >> 6;
    for (int it = 0; it < 2; ++it) {
        int rowbase = blockIdx.x * 64 + it * 32;
        __syncthreads();
        for (int idx = tid; idx < 2048; idx += 256) {
            int r = idx >> 6, c = idx & 63;
            int row = rowbase + r;
            sX[c * 34 + r] = (row < NN) ? state[row * 64 + c] : 0.f;
        }
        __syncthreads();
        unsigned long long acc[4] = {0ull, 0ull, 0ull, 0ull};
#pragma unroll
        for (int k = 0; k < 64; k++) {
            float w = sW[k * 65 + o];
            unsigned long long wp = pk2(w, w);
            const unsigned long long* col =
                (const unsigned long long*)(&sX[k * 34]) + quad * 4;
            fma2(acc[0], col[0], wp);
            fma2(acc[1], col[1], wp);
            fma2(acc[2], col[2], wp);
            fma2(acc[3], col[3], wp);
        }
#pragma unroll
        for (int p = 0; p < 4; p++) {
            float2 hv = up2(acc[p]);
            int r0 = rowbase + quad * 8 + 2 * p;
            if (r0 < NN) {
                float d0 = g_dinv[r0];
                g_h[r0 * 64 + o] = hv.x;
                g_agg[r0 * 64 + o] = hv.x * d0 * d0;
            }
            int r1 = r0 + 1;
            if (r1 < NN) {
                float d1 = g_dinv[r1];
                g_h[r1 * 64 + o] = hv.y;
                g_agg[r1 * 64 + o] = hv.y * d1 * d1;
            }
        }
        __syncthreads();
    }
}

// edge scatter: 16 threads per edge, vectorized fp32 atomics (sm_90+)
__global__ void k_scatter() {
    int t = blockIdx.x * 256 + threadIdx.x;
    int e = t >> 4;
    if (e >= EE) return;
    int c = (t & 15) << 2;
    int s = g_src[e], d = g_dst[e];
    float nrm = g_dinv[s] * g_dinv[d];
    const float4 v = *reinterpret_cast<const float4*>(&g_h[s * 64 + c]);
    float* p = &g_agg[d * 64 + c];
    unsigned long long gp;
    asm("cvta.to.global.u64 %0, %1;" : "=l"(gp) : "l"(p));
    asm volatile("red.global.add.v4.f32 [%0], {%1, %2, %3, %4};" ::"l"(gp),
                 "f"(v.x * nrm), "f"(v.y * nrm), "f"(v.z * nrm), "f"(v.w * nrm)
                 : "memory");
}

__global__ void k_tw1(const float* __restrict__ gW1) {
    int idx = blockIdx.x * 256 + threadIdx.x;
    if (idx >= KIN * GLB) return;
    int k = idx / GLB, j = idx % GLB;
    g_gW1t[idx] = gW1[j * KIN + k];
}

// global branch: xg = leaky(leaky(state_flat @ gW1^T + gb1) @ gW2^T + gb2), 16 b-rows/block
__global__ void k_glob(const float* __restrict__ state, const float* __restrict__ gb1,
                       const float* __restrict__ gW2, const float* __restrict__ gb2) {
    __shared__ float sIn[KIN * 18];   // [k][r], 16 rows padded to 18
    __shared__ float sH[16 * GLB];
    int tid = threadIdx.x;
    int base = blockIdx.x * 16;
    for (int idx = tid; idx < 16 * KIN; idx += 256) {
        int r = idx / KIN, k = idx - r * KIN;
        int b = base + r;
        sIn[k * 18 + r] = (b < BB) ? state[b * KIN + k] : 0.f;
    }
    __syncthreads();
    int j = tid;
    unsigned long long acc[8] = {0ull, 0ull, 0ull, 0ull, 0ull, 0ull, 0ull, 0ull};
#pragma unroll 2
    for (int k = 0; k < KIN; k++) {
        float w = g_gW1t[k * GLB + j];
        unsigned long long wp = pk2(w, w);
        const unsigned long long* col = (const unsigned long long*)(&sIn[k * 18]);
#pragma unroll
        for (int rp = 0; rp < 8; rp++) fma2(acc[rp], col[rp], wp);
    }
    float bj = gb1[j];
#pragma unroll
    for (int rp = 0; rp < 8; rp++) {
        float2 hv = up2(acc[rp]);
        sH[(2 * rp) * GLB + j] = leakyf(hv.x + bj);
        sH[(2 * rp + 1) * GLB + j] = leakyf(hv.y + bj);
    }
    __syncthreads();
    if (tid < 16 * GOUT) {
        int r = tid / GOUT, o = tid - r * GOUT;
        float a = gb2[o];
        const float* hrow = &sH[r * GLB];
        const float* wrow = &gW2[o * GLB];
#pragma unroll 8
        for (int jj = 0; jj < GLB; jj++) a += hrow[jj] * wrow[jj];
        int b = base + r;
        if (b < BB) g_xg[b * GOUT + o] = leakyf(a);
    }
}

// per-node MLP: warp per node, 256 nodes per block
__global__ void k_mlp(const float* __restrict__ state, const float* __restrict__ convb,
                      const float* __restrict__ l1W, const float* __restrict__ l1b,
                      const float* __restrict__ l2W, const float* __restrict__ l2b,
                      const float* __restrict__ l3W, const float* __restrict__ l3b) {
    __shared__ float s1[74 * 32];   // [k][j]
    __shared__ float s2[32 * 32];   // [k][j]
    __shared__ float sb1[32], sb2[32], sw3[32], scb[64];
    __shared__ float sb3;
    __shared__ float sx[8][80];
    int tid = threadIdx.x;
    for (int idx = tid; idx < 74 * 32; idx += 256) {
        int jj = idx / 74, kk = idx - jj * 74;
        s1[kk * 32 + jj] = l1W[idx];
    }
    for (int idx = tid; idx < 32 * 32; idx += 256) {
        int jj = idx >> 5, kk = idx & 31;
        s2[kk * 32 + jj] = l2W[idx];
    }
    if (tid < 32) {
        sb1[tid] = l1b[tid];
        sb2[tid] = l2b[tid];
        sw3[tid] = l3W[tid];
    }
    if (tid < 64) scb[tid] = convb[tid];
    if (tid == 0) sb3 = l3b[0];
    __syncthreads();

    int w = tid >> 5, j = tid & 31;
    float lsum = 0.f;
    int basen = blockIdx.x * 256;
    for (int it = 0; it < 32; ++it) {
        int i = basen + it * 8 + w;
        if (i < NN) {
            int b = i / ACTD;
            float a0 = g_agg[i * 64 + j] + scb[j];
            float a1 = g_agg[i * 64 + 32 + j] + scb[32 + j];
            a0 = fmaxf(a0, 0.f) + state[i * 64 + j];
            a1 = fmaxf(a1, 0.f) + state[i * 64 + 32 + j];
            sx[w][j] = a0;
            sx[w][32 + j] = a1;
            if (j < GOUT) sx[w][64 + j] = g_xg[b * GOUT + j];
            __syncwarp();
            float acc = sb1[j];
#pragma unroll
            for (int k = 0; k < 74; k++) acc += sx[w][k] * s1[k * 32 + j];
            float h1 = leakyf(acc);
            __syncwarp();   // all sx reads done before next iteration overwrites
            float acc2 = sb2[j];
#pragma unroll
            for (int k = 0; k < 32; k++)
                acc2 += __shfl_sync(0xffffffffu, h1, k) * s2[k * 32 + j];
            float h2 = leakyf(acc2);
            float v = h2 * sw3[j];
#pragma unroll
            for (int off = 16; off; off >>= 1) v += __shfl_xor_sync(0xffffffffu, v, off);
            float conc = softplusf(v + sb3);
            if (j == 0) {
                g_conc[i] = conc;
                lsum += conc;
            }
        }
    }
    if (j == 0) atomicAdd(&g_sum, lsum);
}

__global__ void k_final(float* __restrict__ out) {
    int b = blockIdx.x * 256 + threadIdx.x;
    if (b >= BB) return;
    float c[ACTD];
    float s = 0.f;
#pragma unroll
    for (int a = 0; a < ACTD; a++) {
        c[a] = g_conc[b * ACTD + a];
        s += c[a];
    }
    float inv = 1.f / (s + 1e-20f);
#pragma unroll
    for (int a = 0; a < ACTD; a++) out[b * ACTD + a] = c[a] * inv;
}

__global__ void k_reg(float* __restrict__ out) {
    out[NN] = g_sum * (1.0f / (float)NN);
}

// ---------------- launch ----------------
extern "C" void kernel_launch(void* const* d_in, const int* in_sizes, int n_in,
                              void* d_out, int out_size) {
    const float* state = (const float*)d_in[0];
    const void*  eidx  = d_in[1];
    const float* convW = (const float*)d_in[2];
    const float* convb = (const float*)d_in[3];
    const float* gW1   = (const float*)d_in[4];
    const float* gb1   = (const float*)d_in[5];
    const float* gW2   = (const float*)d_in[6];
    const float* gb2   = (const float*)d_in[7];
    const float* l1W   = (const float*)d_in[8];
    const float* l1b   = (const float*)d_in[9];
    const float* l2W   = (const float*)d_in[10];
    const float* l2b   = (const float*)d_in[11];
    const float* l3W   = (const float*)d_in[12];
    const float* l3b   = (const float*)d_in[13];
    float* out = (float*)d_out;

    k_zero<<<(NN + 255) / 256, 256>>>();
    k_edges<<<(EE + 255) / 256, 256>>>(eidx);
    k_dinv<<<(NN + 255) / 256, 256>>>();
    k_conv<<<(NN + 63) / 64, 256>>>(state, convW);
    k_scatter<<<(EE * 16) / 256, 256>>>();
    k_tw1<<<(KIN * GLB) / 256, 256>>>(gW1);
    k_glob<<<(BB + 15) / 16, 256>>>(state, gb1, gW2, gb2);
    k_mlp<<<(NN + 255) / 256, 256>>>(state, convb, l1W, l1b, l2W, l2b, l3W, l3b);
    k_final<<<(BB + 255) / 256, 256>>>(out);
    if (out_size > NN) k_reg<<<1, 1>>>(out);
}

// round 2
// speedup vs baseline: 1.2392x; 1.2392x over previous
#include <cuda_runtime.h>

#define NN   150000
#define EE   1200000
#define ACTD 6
#define BB   25000
#define GLB  256
#define GOUT 10
#define KIN  384

typedef unsigned long long ull;

// ---------------- static device scratch ----------------
__device__ __align__(16) float g_h2[NN * 64];    // (state @ convW^T) * dinv[i]
__device__ __align__(16) float g_agg[NN * 64];   // un-dst-normalized aggregation
__device__ float g_deg[NN];
__device__ float g_dinv[NN];
__device__ int   g_src[EE];
__device__ int   g_dst[EE];
__device__ float g_gW1t[KIN * GLB];              // gW1 transposed [k][j]
__device__ float g_xg[BB * GOUT];
__device__ float g_conc[NN];
__device__ float g_sum;

// ---------------- helpers ----------------
__device__ __forceinline__ float leakyf(float x) { return x > 0.f ? x : 0.01f * x; }
__device__ __forceinline__ float softplusf(float x) {
    return fmaxf(x, 0.f) + log1pf(expf(-fabsf(x)));
}
__device__ __forceinline__ ull pk2(float x, float y) {
    ull r;
    asm("mov.b64 %0, {%1, %2};" : "=l"(r) : "f"(x), "f"(y));
    return r;
}
__device__ __forceinline__ void fma2(ull& d, ull a, ull b) {
    asm("fma.rn.f32x2 %0, %1, %2, %3;" : "=l"(d) : "l"(a), "l"(b), "l"(d));
}
__device__ __forceinline__ float2 up2(ull v) {
    float lo, hi;
    asm("mov.b64 {%0, %1}, %2;" : "=f"(lo), "=f"(hi) : "l"(v));
    return make_float2(lo, hi);
}

// ---------------- small kernels ----------------
__global__ void k_zero() {
    int i = blockIdx.x * 256 + threadIdx.x;
    if (i < NN) g_deg[i] = 0.f;
    if (i == 0) g_sum = 0.f;
}

__global__ void k_edges(const void* __restrict__ eidx) {
    int e = blockIdx.x * 256 + threadIdx.x;
    if (e >= EE) return;
    const long long* p64 = (const long long*)eidx;
    bool is64 = true;
#pragma unroll
    for (int t = 0; t < 8; t++) {
        unsigned long long v = (unsigned long long)p64[t];
        if (v >= (unsigned long long)NN) is64 = false;
    }
    int s, d;
    if (is64) { s = (int)p64[e]; d = (int)p64[EE + e]; }
    else      { const int* p32 = (const int*)eidx; s = p32[e]; d = p32[EE + e]; }
    g_src[e] = s;
    g_dst[e] = d;
    atomicAdd(&g_deg[d], 1.0f);
}

__global__ void k_dinv() {
    int i = blockIdx.x * 256 + threadIdx.x;
    if (i < NN) g_dinv[i] = rsqrtf(g_deg[i] + 1.0f);
}

__global__ void k_tw1(const float* __restrict__ gW1) {
    int idx = blockIdx.x * 256 + threadIdx.x;
    if (idx >= KIN * GLB) return;
    int k = idx / GLB, j = idx % GLB;
    g_gW1t[idx] = gW1[j * KIN + k];
}

// ---------------- k_conv: h2 = (state @ W^T)*dinv, agg init = h2 ----------------
// block: 128 rows x 64 cols, 256 threads = 8 warps (4 rowgrp x 2 colgrp)
// warp tile 32x32; thread tile 4 rows x 8 cols
#define CONV_SX 0             // [64][132]
#define CONV_SW (64 * 132)    // [64][68]
#define CONV_SMEM ((64 * 132 + 64 * 68) * 4)
__global__ __launch_bounds__(256) void k_conv(const float* __restrict__ state,
                                              const float* __restrict__ convW) {
    extern __shared__ float sm[];
    float* sX = sm + CONV_SX;
    float* sW = sm + CONV_SW;
    int tid = threadIdx.x;
    int base = blockIdx.x * 128;

    for (int idx = tid; idx < 4096; idx += 256) {
        int o = idx >> 6, k = idx & 63;
        sW[k * 68 + o] = convW[idx];
    }
    for (int idx = tid; idx < 128 * 64; idx += 256) {
        int r = idx >> 6, k = idx & 63;
        int row = base + r;
        sX[k * 132 + r] = (row < NN) ? state[row * 64 + k] : 0.f;
    }
    __syncthreads();

    int warp = tid >> 5, lane = tid & 31;
    int rg = lane >> 2, cg = lane & 3;
    int wr = (warp >> 1) * 32, wc = (warp & 1) * 32;
    int rowb = wr + rg * 4;
    int colb = wc + cg * 8;

    ull acc[4][4];
#pragma unroll
    for (int r = 0; r < 4; r++)
#pragma unroll
        for (int c = 0; c < 4; c++) acc[r][c] = 0ull;

#pragma unroll 8
    for (int k = 0; k < 64; k++) {
        float4 xv = *(const float4*)&sX[k * 132 + rowb];
        ull xp[4] = {pk2(xv.x, xv.x), pk2(xv.y, xv.y), pk2(xv.z, xv.z), pk2(xv.w, xv.w)};
        const ulonglong2* wp = (const ulonglong2*)&sW[k * 68 + colb];
        ulonglong2 wa = wp[0], wb = wp[1];
#pragma unroll
        for (int r = 0; r < 4; r++) {
            fma2(acc[r][0], xp[r], wa.x);
            fma2(acc[r][1], xp[r], wa.y);
            fma2(acc[r][2], xp[r], wb.x);
            fma2(acc[r][3], xp[r], wb.y);
        }
    }

#pragma unroll
    for (int r = 0; r < 4; r++) {
        int row = base + rowb + r;
        if (row >= NN) continue;
        float di = g_dinv[row];
        float2 v0 = up2(acc[r][0]), v1 = up2(acc[r][1]);
        float2 v2 = up2(acc[r][2]), v3 = up2(acc[r][3]);
        float4 fa = make_float4(v0.x * di, v0.y * di, v1.x * di, v1.y * di);
        float4 fb = make_float4(v2.x * di, v2.y * di, v3.x * di, v3.y * di);
        *(float4*)&g_h2[row * 64 + colb] = fa;
        *(float4*)&g_h2[row * 64 + colb + 4] = fb;
        *(float4*)&g_agg[row * 64 + colb] = fa;
        *(float4*)&g_agg[row * 64 + colb + 4] = fb;
    }
}

// ---------------- k_scatter ----------------
__global__ void k_scatter() {
    int t = blockIdx.x * 256 + threadIdx.x;
    int e = t >> 4;
    if (e >= EE) return;
    int c = (t & 15) << 2;
    int s = g_src[e], d = g_dst[e];
    const float4 v = *reinterpret_cast<const float4*>(&g_h2[s * 64 + c]);
    float* p = &g_agg[d * 64 + c];
    unsigned long long gp;
    asm("cvta.to.global.u64 %0, %1;" : "=l"(gp) : "l"(p));
    asm volatile("red.global.add.v4.f32 [%0], {%1, %2, %3, %4};" ::"l"(gp),
                 "f"(v.x), "f"(v.y), "f"(v.z), "f"(v.w)
                 : "memory");
}

// ---------------- k_glob ----------------
// block: 32 rows x 256 cols, 256 threads = 8 warps (col-split)
// warp tile 32x32, thread tile 4x8; W streamed in K-chunks of 32
#define GLOB_SIN 0                       // [384][36]
#define GLOB_SU  (384 * 36)              // union: W chunk [32][256] / H [32][260]
#define GLOB_SB1 (GLOB_SU + 32 * 260)    // [256]
#define GLOB_SMEM ((GLOB_SB1 + 256) * 4)
__global__ __launch_bounds__(256) void k_glob(const float* __restrict__ state,
                                              const float* __restrict__ gb1,
                                              const float* __restrict__ gW2,
                                              const float* __restrict__ gb2) {
    extern __shared__ float sm[];
    float* sIn = sm + GLOB_SIN;
    float* sU = sm + GLOB_SU;
    float* sb1 = sm + GLOB_SB1;
    int tid = threadIdx.x;
    int base = blockIdx.x * 32;

    for (int idx = tid; idx < 32 * KIN; idx += 256) {
        int r = idx / KIN, k = idx - r * KIN;
        int b = base + r;
        sIn[k * 36 + r] = (b < BB) ? state[b * KIN + k] : 0.f;
    }
    sb1[tid] = gb1[tid];

    int warp = tid >> 5, lane = tid & 31;
    int rg = lane >> 2, cg = lane & 3;
    int rowb = rg * 4;
    int colb = warp * 32 + cg * 8;

    ull acc[4][4];
#pragma unroll
    for (int r = 0; r < 4; r++)
#pragma unroll
        for (int c = 0; c < 4; c++) acc[r][c] = 0ull;

    for (int kc = 0; kc < KIN; kc += 32) {
        __syncthreads();
        for (int idx = tid; idx < 32 * 256; idx += 256)
            sU[idx] = g_gW1t[(kc + (idx >> 8)) * 256 + (idx & 255)];
        __syncthreads();
#pragma unroll 8
        for (int kk = 0; kk < 32; kk++) {
            float4 xv = *(const float4*)&sIn[(kc + kk) * 36 + rowb];
            ull xp[4] = {pk2(xv.x, xv.x), pk2(xv.y, xv.y), pk2(xv.z, xv.z), pk2(xv.w, xv.w)};
            const ulonglong2* wp = (const ulonglong2*)&sU[kk * 256 + colb];
            ulonglong2 wa = wp[0], wb = wp[1];
#pragma unroll
            for (int r = 0; r < 4; r++) {
                fma2(acc[r][0], xp[r], wa.x);
                fma2(acc[r][1], xp[r], wa.y);
                fma2(acc[r][2], xp[r], wb.x);
                fma2(acc[r][3], xp[r], wb.y);
            }
        }
    }

    __syncthreads();   // done reading W region; reuse as H
#pragma unroll
    for (int r = 0; r < 4; r++) {
        int row = rowb + r;
#pragma unroll
        for (int cp = 0; cp < 4; cp++) {
            int c = colb + cp * 2;
            float2 v = up2(acc[r][cp]);
            float2 h;
            h.x = leakyf(v.x + sb1[c]);
            h.y = leakyf(v.y + sb1[c + 1]);
            *(float2*)&sU[row * 260 + c] = h;
        }
    }
    __syncthreads();

    // layer 2: [32 x 256] @ gW2^T[256 x 10]
    for (int t = tid; t < 32 * GOUT; t += 256) {
        int r = t / GOUT, o = t - r * GOUT;
        float a = gb2[o];
        const float* hr = &sU[r * 260];
        const float* wr = &gW2[o * GLB];
#pragma unroll 8
        for (int j = 0; j < GLB; j++) a += hr[j] * wr[j];
        int b = base + r;
        if (b < BB) g_xg[b * GOUT + o] = leakyf(a);
    }
}

// ---------------- k_mlp ----------------
// block: 128 nodes, 128 threads = 4 warps; warp tile 32 rows x 32 cols (full H)
#define MLP_SX  0                   // [74][132]
#define MLP_SH  (74 * 132)          // [32][132]
#define MLP_SW1 (MLP_SH + 32 * 132) // [74][32]
#define MLP_SW2 (MLP_SW1 + 74 * 32) // [32][32]
#define MLP_SCB (MLP_SW2 + 32 * 32) // [64]
#define MLP_SB1 (MLP_SCB + 64)      // [32]
#define MLP_SB2 (MLP_SB1 + 32)      // [32]
#define MLP_SW3 (MLP_SB2 + 32)      // [32]
#define MLP_SB3 (MLP_SW3 + 32)      // [1]
#define MLP_SMEM ((MLP_SB3 + 4) * 4)
__global__ __launch_bounds__(128) void k_mlp(const float* __restrict__ state,
                                             const float* __restrict__ convb,
                                             const float* __restrict__ l1W,
                                             const float* __restrict__ l1b,
                                             const float* __restrict__ l2W,
                                             const float* __restrict__ l2b,
                                             const float* __restrict__ l3W,
                                             const float* __restrict__ l3b) {
    extern __shared__ float sm[];
    float* sX = sm + MLP_SX;
    float* sH = sm + MLP_SH;
    float* sW1 = sm + MLP_SW1;
    float* sW2 = sm + MLP_SW2;
    float* scb = sm + MLP_SCB;
    float* sb1 = sm + MLP_SB1;
    float* sb2 = sm + MLP_SB2;
    float* sw3 = sm + MLP_SW3;
    float* sb3 = sm + MLP_SB3;

    int tid = threadIdx.x;
    int base = blockIdx.x * 128;

    if (tid < 64) scb[tid] = convb[tid];
    if (tid < 32) {
        sb1[tid] = l1b[tid];
        sb2[tid] = l2b[tid];
        sw3[tid] = l3W[tid];
    }
    if (tid == 0) sb3[0] = l3b[0];
    for (int idx = tid; idx < 74 * 32; idx += 128) {
        int j = idx / 74, k = idx - j * 74;
        sW1[k * 32 + j] = l1W[idx];
    }
    for (int idx = tid; idx < 32 * 32; idx += 128) {
        int j = idx >> 5, k = idx & 31;
        sW2[k * 32 + j] = l2W[idx];
    }
    __syncthreads();   // scb ready before X build uses it

    // build X: [74][128]  (first 64 = relu(agg*dinv + cb) + state, last 10 = xg)
    for (int idx = tid; idx < 128 * 64; idx += 128) {
        int r = idx >> 6, k = idx & 63;
        int row = base + r;
        float v = 0.f;
        if (row < NN) {
            float a = g_agg[row * 64 + k] * g_dinv[row] + scb[k];
            v = fmaxf(a, 0.f) + state[row * 64 + k];
        }
        sX[k * 132 + r] = v;
    }
    for (int idx = tid; idx < 128 * 10; idx += 128) {
        int r = idx / 10, k = idx - r * 10;
        int row = base + r;
        sX[(64 + k) * 132 + r] = (row < NN) ? g_xg[(row / ACTD) * 10 + k] : 0.f;
    }
    __syncthreads();

    int warp = tid >> 5, lane = tid & 31;
    int rg = lane >> 2, cg = lane & 3;
    int rowb = warp * 32 + rg * 4;
    int colb = cg * 8;

    // GEMM1: [128 x 74] @ W1[74 x 32]
    ull acc[4][4];
#pragma unroll
    for (int r = 0; r < 4; r++)
#pragma unroll
        for (int c = 0; c < 4; c++) acc[r][c] = 0ull;
#pragma unroll 2
    for (int k = 0; k < 74; k++) {
        float4 xv = *(const float4*)&sX[k * 132 + rowb];
        ull xp[4] = {pk2(xv.x, xv.x), pk2(xv.y, xv.y), pk2(xv.z, xv.z), pk2(xv.w, xv.w)};
        const ulonglong2* wp = (const ulonglong2*)&sW1[k * 32 + colb];
        ulonglong2 wa = wp[0], wb = wp[1];
#pragma unroll
        for (int r = 0; r < 4; r++) {
            fma2(acc[r][0], xp[r], wa.x);
            fma2(acc[r][1], xp[r], wa.y);
            fma2(acc[r][2], xp[r], wb.x);
            fma2(acc[r][3], xp[r], wb.y);
        }
    }
    // h1 = leaky(acc + b1), store transposed [j][node]
    {
        float hv[4][8];
#pragma unroll
        for (int r = 0; r < 4; r++)
#pragma unroll
            for (int cp = 0; cp < 4; cp++) {
                float2 v = up2(acc[r][cp]);
                int c = colb + cp * 2;
                hv[r][cp * 2] = leakyf(v.x + sb1[c]);
                hv[r][cp * 2 + 1] = leakyf(v.y + sb1[c + 1]);
            }
#pragma unroll
        for (int c = 0; c < 8; c++) {
            float4 f = make_float4(hv[0][c], hv[1][c], hv[2][c], hv[3][c]);
            *(float4*)&sH[(colb + c) * 132 + rowb] = f;
        }
    }
    __syncthreads();

    // GEMM2: [128 x 32] @ W2[32 x 32]
#pragma unroll
    for (int r = 0; r < 4; r++)
#pragma unroll
        for (int c = 0; c < 4; c++) acc[r][c] = 0ull;
#pragma unroll 4
    for (int k = 0; k < 32; k++) {
        float4 xv = *(const float4*)&sH[k * 132 + rowb];
        ull xp[4] = {pk2(xv.x, xv.x), pk2(xv.y, xv.y), pk2(xv.z, xv.z), pk2(xv.w, xv.w)};
        const ulonglong2* wp = (const ulonglong2*)&sW2[k * 32 + colb];
        ulonglong2 wa = wp[0], wb = wp[1];
#pragma unroll
        for (int r = 0; r < 4; r++) {
            fma2(acc[r][0], xp[r], wa.x);
            fma2(acc[r][1], xp[r], wa.y);
            fma2(acc[r][2], xp[r], wb.x);
            fma2(acc[r][3], xp[r], wb.y);
        }
    }

    // layer3: per-row dot over 32 cols, softplus, write conc + sum
    float srow[4];
#pragma unroll
    for (int r = 0; r < 4; r++) {
        float s = 0.f;
#pragma unroll
        for (int cp = 0; cp < 4; cp++) {
            float2 v = up2(acc[r][cp]);
            int c = colb + cp * 2;
            float h0 = leakyf(v.x + sb2[c]);
            float h1 = leakyf(v.y + sb2[c + 1]);
            s += h0 * sw3[c] + h1 * sw3[c + 1];
        }
        srow[r] = s;
    }
#pragma unroll
    for (int r = 0; r < 4; r++) {
        srow[r] += __shfl_xor_sync(0xffffffffu, srow[r], 1);
        srow[r] += __shfl_xor_sync(0xffffffffu, srow[r], 2);
    }
    float lsum = 0.f;
    if (cg == 0) {
        float b3 = sb3[0];
#pragma unroll
        for (int r = 0; r < 4; r++) {
            int node = base + rowb + r;
            if (node < NN) {
                float conc = softplusf(srow[r] + b3);
                g_conc[node] = conc;
                lsum += conc;
            }
        }
    }
#pragma unroll
    for (int off = 16; off; off >>= 1) lsum += __shfl_xor_sync(0xffffffffu, lsum, off);
    if (lane == 0) atomicAdd(&g_sum, lsum);
}

// ---------------- finalize ----------------
__global__ void k_final(float* __restrict__ out) {
    int b = blockIdx.x * 256 + threadIdx.x;
    if (b >= BB) return;
    float c[ACTD];
    float s = 0.f;
#pragma unroll
    for (int a = 0; a < ACTD; a++) {
        c[a] = g_conc[b * ACTD + a];
        s += c[a];
    }
    float inv = 1.f / (s + 1e-20f);
#pragma unroll
    for (int a = 0; a < ACTD; a++) out[b * ACTD + a] = c[a] * inv;
}

__global__ void k_reg(float* __restrict__ out) {
    out[NN] = g_sum * (1.0f / (float)NN);
}

// ---------------- launch ----------------
extern "C" void kernel_launch(void* const* d_in, const int* in_sizes, int n_in,
                              void* d_out, int out_size) {
    const float* state = (const float*)d_in[0];
    const void*  eidx  = d_in[1];
    const float* convW = (const float*)d_in[2];
    const float* convb = (const float*)d_in[3];
    const float* gW1   = (const float*)d_in[4];
    const float* gb1   = (const float*)d_in[5];
    const float* gW2   = (const float*)d_in[6];
    const float* gb2   = (const float*)d_in[7];
    const float* l1W   = (const float*)d_in[8];
    const float* l1b   = (const float*)d_in[9];
    const float* l2W   = (const float*)d_in[10];
    const float* l2b   = (const float*)d_in[11];
    const float* l3W   = (const float*)d_in[12];
    const float* l3b   = (const float*)d_in[13];
    float* out = (float*)d_out;

    cudaFuncSetAttribute(k_conv, cudaFuncAttributeMaxDynamicSharedMemorySize, CONV_SMEM);
    cudaFuncSetAttribute(k_glob, cudaFuncAttributeMaxDynamicSharedMemorySize, GLOB_SMEM);
    cudaFuncSetAttribute(k_mlp,  cudaFuncAttributeMaxDynamicSharedMemorySize, MLP_SMEM);

    k_zero<<<(NN + 255) / 256, 256>>>();
    k_edges<<<(EE + 255) / 256, 256>>>(eidx);
    k_dinv<<<(NN + 255) / 256, 256>>>();
    k_conv<<<(NN + 127) / 128, 256, CONV_SMEM>>>(state, convW);
    k_scatter<<<(EE * 16) / 256, 256>>>();
    k_tw1<<<(KIN * GLB) / 256, 256>>>(gW1);
    k_glob<<<(BB + 31) / 32, 256, GLOB_SMEM>>>(state, gb1, gW2, gb2);
    k_mlp<<<(NN + 127) / 128, 128, MLP_SMEM>>>(state, convb, l1W, l1b, l2W, l2b, l3W, l3b);
    k_final<<<(BB + 255) / 256, 256>>>(out);
    if (out_size > NN) k_reg<<<1, 1>>>(out);
}

// round 3
// speedup vs baseline: 1.2885x; 1.0398x over previous
#include <cuda_runtime.h>

#define NN   150000
#define EE   1200000
#define ACTD 6
#define BB   25000
#define GLB  256
#define GOUT 10
#define KIN  384

typedef unsigned long long ull;

// ---------------- static device scratch ----------------
__device__ __align__(16) float g_h2[NN * 64];    // (state @ convW^T) * dinv[i]
__device__ __align__(16) float g_agg[NN * 64];   // aggregation (un-dst-normalized)
__device__ float g_deg[NN];
__device__ float g_dinv[NN];
__device__ __align__(8) int2 g_sd[EE];
__device__ int   g_is64;
__device__ float g_gW1t[KIN * GLB];              // gW1 transposed [k][j]
__device__ float g_xg[BB * GOUT];
__device__ float g_conc[NN];
__device__ float g_sum;

// ---------------- helpers ----------------
__device__ __forceinline__ float leakyf(float x) { return x > 0.f ? x : 0.01f * x; }
__device__ __forceinline__ float softplusf(float x) {
    return fmaxf(x, 0.f) + log1pf(expf(-fabsf(x)));
}
__device__ __forceinline__ ull pk2(float x, float y) {
    ull r;
    asm("mov.b64 %0, {%1, %2};" : "=l"(r) : "f"(x), "f"(y));
    return r;
}
__device__ __forceinline__ void fma2(ull& d, ull a, ull b) {
    asm("fma.rn.f32x2 %0, %1, %2, %3;" : "=l"(d) : "l"(a), "l"(b), "l"(d));
}
__device__ __forceinline__ float2 up2(ull v) {
    float lo, hi;
    asm("mov.b64 {%0, %1}, %2;" : "=f"(lo), "=f"(hi) : "l"(v));
    return make_float2(lo, hi);
}

// ---------------- small kernels ----------------
__global__ void k_zero(const void* __restrict__ eidx) {
    int i = blockIdx.x * 256 + threadIdx.x;
    if (i < NN) g_deg[i] = 0.f;
    if (i == 0) {
        g_sum = 0.f;
        const long long* p64 = (const long long*)eidx;
        int is64 = 1;
#pragma unroll
        for (int t = 0; t < 8; t++) {
            unsigned long long v = (unsigned long long)p64[t];
            if (v >= (unsigned long long)NN) is64 = 0;
        }
        g_is64 = is64;
    }
}

__global__ void k_edges(const void* __restrict__ eidx) {
    int e = blockIdx.x * 256 + threadIdx.x;
    if (e >= EE) return;
    int s, d;
    if (g_is64) {
        const long long* p64 = (const long long*)eidx;
        s = (int)p64[e];
        d = (int)p64[EE + e];
    } else {
        const int* p32 = (const int*)eidx;
        s = p32[e];
        d = p32[EE + e];
    }
    g_sd[e] = make_int2(s, d);
    atomicAdd(&g_deg[d], 1.0f);
}

__global__ void k_dinv() {
    int i = blockIdx.x * 256 + threadIdx.x;
    if (i < NN) g_dinv[i] = rsqrtf(g_deg[i] + 1.0f);
}

__global__ void k_tw1(const float* __restrict__ gW1) {
    int idx = blockIdx.x * 256 + threadIdx.x;
    if (idx >= KIN * GLB) return;
    int k = idx / GLB, j = idx % GLB;
    g_gW1t[idx] = gW1[j * KIN + k];
}

// ---------------- k_conv ----------------
// block: 128 rows x 64 cols, 256 threads, warp tile 32x32, thread tile 4x8
#define CONV_SX 0             // [64][132]
#define CONV_SW (64 * 132)    // [64][68]
#define CONV_SMEM ((64 * 132 + 64 * 68) * 4)
__global__ __launch_bounds__(256) void k_conv(const float* __restrict__ state,
                                              const float* __restrict__ convW) {
    extern __shared__ float sm[];
    float* sX = sm + CONV_SX;
    float* sW = sm + CONV_SW;
    int tid = threadIdx.x;
    int base = blockIdx.x * 128;

    for (int idx = tid; idx < 4096; idx += 256) {
        int o = idx >> 6, k = idx & 63;
        sW[k * 68 + o] = convW[idx];
    }
    // vectorized X fill: 8 LDG.128 per thread
    for (int idx = tid; idx < 2048; idx += 256) {
        int r = idx >> 4, kq = (idx & 15) << 2;
        int row = base + r;
        float4 v = (row < NN) ? *(const float4*)&state[row * 64 + kq]
                              : make_float4(0.f, 0.f, 0.f, 0.f);
        sX[(kq + 0) * 132 + r] = v.x;
        sX[(kq + 1) * 132 + r] = v.y;
        sX[(kq + 2) * 132 + r] = v.z;
        sX[(kq + 3) * 132 + r] = v.w;
    }

    int warp = tid >> 5, lane = tid & 31;
    int rg = lane >> 2, cg = lane & 3;
    int rowb = (warp >> 1) * 32 + rg * 4;
    int colb = (warp & 1) * 32 + cg * 8;

    // prefetch dinv before the GEMM (independent)
    float di[4];
#pragma unroll
    for (int r = 0; r < 4; r++) {
        int row = base + rowb + r;
        di[r] = (row < NN) ? g_dinv[row] : 0.f;
    }
    __syncthreads();

    ull acc[4][4];
#pragma unroll
    for (int r = 0; r < 4; r++)
#pragma unroll
        for (int c = 0; c < 4; c++) acc[r][c] = 0ull;

#pragma unroll 16
    for (int k = 0; k < 64; k++) {
        float4 xv = *(const float4*)&sX[k * 132 + rowb];
        ull xp[4] = {pk2(xv.x, xv.x), pk2(xv.y, xv.y), pk2(xv.z, xv.z), pk2(xv.w, xv.w)};
        const ulonglong2* wp = (const ulonglong2*)&sW[k * 68 + colb];
        ulonglong2 wa = wp[0], wb = wp[1];
#pragma unroll
        for (int r = 0; r < 4; r++) {
            fma2(acc[r][0], xp[r], wa.x);
            fma2(acc[r][1], xp[r], wa.y);
            fma2(acc[r][2], xp[r], wb.x);
            fma2(acc[r][3], xp[r], wb.y);
        }
    }

#pragma unroll
    for (int r = 0; r < 4; r++) {
        int row = base + rowb + r;
        if (row >= NN) continue;
        float2 v0 = up2(acc[r][0]), v1 = up2(acc[r][1]);
        float2 v2 = up2(acc[r][2]), v3 = up2(acc[r][3]);
        float4 fa = make_float4(v0.x * di[r], v0.y * di[r], v1.x * di[r], v1.y * di[r]);
        float4 fb = make_float4(v2.x * di[r], v2.y * di[r], v3.x * di[r], v3.y * di[r]);
        *(float4*)&g_h2[row * 64 + colb] = fa;
        *(float4*)&g_h2[row * 64 + colb + 4] = fb;
        *(float4*)&g_agg[row * 64 + colb] = fa;
        *(float4*)&g_agg[row * 64 + colb + 4] = fb;
    }
}

// ---------------- k_scatter: 8 threads/edge, 2x red.v4 each ----------------
__global__ void k_scatter() {
    int t = blockIdx.x * 256 + threadIdx.x;
    int e = t >> 3;
    if (e >= EE) return;
    int c = (t & 7) << 3;   // 0,8,...,56
    int2 sd = g_sd[e];
    const float4* src = (const float4*)&g_h2[sd.x * 64 + c];
    float4 v0 = src[0];
    float4 v1 = src[1];
    float* p = &g_agg[sd.y * 64 + c];
    unsigned long long gp;
    asm("cvta.to.global.u64 %0, %1;" : "=l"(gp) : "l"(p));
    asm volatile("red.global.add.v4.f32 [%0], {%1, %2, %3, %4};" ::"l"(gp),
                 "f"(v0.x), "f"(v0.y), "f"(v0.z), "f"(v0.w) : "memory");
    asm volatile("red.global.add.v4.f32 [%0], {%1, %2, %3, %4};" ::"l"(gp + 16),
                 "f"(v1.x), "f"(v1.y), "f"(v1.z), "f"(v1.w) : "memory");
}

// ---------------- k_glob: 64 rows x 256 cols, 512 threads ----------------
#define GLOB_SIN 0                        // [384][68]
#define GLOB_SU  (384 * 68)               // union: W chunk [32][256] / H [64][260]
#define GLOB_SB1 (GLOB_SU + 64 * 260)     // [256]
#define GLOB_SMEM ((GLOB_SB1 + 256) * 4)
__global__ __launch_bounds__(512) void k_glob(const float* __restrict__ state,
                                              const float* __restrict__ gb1,
                                              const float* __restrict__ gW2,
                                              const float* __restrict__ gb2) {
    extern __shared__ float sm[];
    float* sIn = sm + GLOB_SIN;
    float* sU = sm + GLOB_SU;
    float* sb1 = sm + GLOB_SB1;
    int tid = threadIdx.x;
    int base = blockIdx.x * 64;

    for (int idx = tid; idx < 64 * KIN; idx += 512) {
        int r = idx / KIN, k = idx - r * KIN;
        int b = base + r;
        sIn[k * 68 + r] = (b < BB) ? state[b * KIN + k] : 0.f;
    }
    if (tid < 256) sb1[tid] = gb1[tid];

    int warp = tid >> 5, lane = tid & 31;
    int rg = lane >> 2, cg = lane & 3;
    int rowb = (warp >> 3) * 32 + rg * 4;
    int colb = (warp & 7) * 32 + cg * 8;

    ull acc[4][4];
#pragma unroll
    for (int r = 0; r < 4; r++)
#pragma unroll
        for (int c = 0; c < 4; c++) acc[r][c] = 0ull;

    for (int kc = 0; kc < KIN; kc += 32) {
        __syncthreads();
        for (int idx = tid; idx < 32 * 256; idx += 512)
            sU[idx] = g_gW1t[kc * 256 + idx];
        __syncthreads();
#pragma unroll 8
        for (int kk = 0; kk < 32; kk++) {
            float4 xv = *(const float4*)&sIn[(kc + kk) * 68 + rowb];
            ull xp[4] = {pk2(xv.x, xv.x), pk2(xv.y, xv.y), pk2(xv.z, xv.z), pk2(xv.w, xv.w)};
            const ulonglong2* wp = (const ulonglong2*)&sU[kk * 256 + colb];
            ulonglong2 wa = wp[0], wb = wp[1];
#pragma unroll
            for (int r = 0; r < 4; r++) {
                fma2(acc[r][0], xp[r], wa.x);
                fma2(acc[r][1], xp[r], wa.y);
                fma2(acc[r][2], xp[r], wb.x);
                fma2(acc[r][3], xp[r], wb.y);
            }
        }
    }

    __syncthreads();   // done reading W region; reuse as H [64][260]
#pragma unroll
    for (int r = 0; r < 4; r++) {
        int row = rowb + r;
#pragma unroll
        for (int cp = 0; cp < 4; cp++) {
            int c = colb + cp * 2;
            float2 v = up2(acc[r][cp]);
            float2 h;
            h.x = leakyf(v.x + sb1[c]);
            h.y = leakyf(v.y + sb1[c + 1]);
            *(float2*)&sU[row * 260 + c] = h;
        }
    }
    __syncthreads();

    // layer 2: [64 x 256] @ gW2^T[256 x 10]
    for (int t = tid; t < 64 * GOUT; t += 512) {
        int r = t / GOUT, o = t - r * GOUT;
        float a = gb2[o];
        const float* hr = &sU[r * 260];
        const float* wr = &gW2[o * GLB];
#pragma unroll 8
        for (int j = 0; j < GLB; j++) a += hr[j] * wr[j];
        int b = base + r;
        if (b < BB) g_xg[b * GOUT + o] = leakyf(a);
    }
}

// ---------------- k_mlp ----------------
#define MLP_SX  0                   // [74][132]
#define MLP_SH  (74 * 132)          // [32][132]
#define MLP_SW1 (MLP_SH + 32 * 132) // [74][32]
#define MLP_SW2 (MLP_SW1 + 74 * 32) // [32][32]
#define MLP_SCB (MLP_SW2 + 32 * 32) // [64]
#define MLP_SB1 (MLP_SCB + 64)      // [32]
#define MLP_SB2 (MLP_SB1 + 32)      // [32]
#define MLP_SW3 (MLP_SB2 + 32)      // [32]
#define MLP_SB3 (MLP_SW3 + 32)      // [1]
#define MLP_SMEM ((MLP_SB3 + 4) * 4)
__global__ __launch_bounds__(128) void k_mlp(const float* __restrict__ state,
                                             const float* __restrict__ convb,
                                             const float* __restrict__ l1W,
                                             const float* __restrict__ l1b,
                                             const float* __restrict__ l2W,
                                             const float* __restrict__ l2b,
                                             const float* __restrict__ l3W,
                                             const float* __restrict__ l3b) {
    extern __shared__ float sm[];
    float* sX = sm + MLP_SX;
    float* sH = sm + MLP_SH;
    float* sW1 = sm + MLP_SW1;
    float* sW2 = sm + MLP_SW2;
    float* scb = sm + MLP_SCB;
    float* sb1 = sm + MLP_SB1;
    float* sb2 = sm + MLP_SB2;
    float* sw3 = sm + MLP_SW3;
    float* sb3 = sm + MLP_SB3;

    int tid = threadIdx.x;
    int base = blockIdx.x * 128;

    if (tid < 64) scb[tid] = convb[tid];
    if (tid < 32) {
        sb1[tid] = l1b[tid];
        sb2[tid] = l2b[tid];
        sw3[tid] = l3W[tid];
    }
    if (tid == 0) sb3[0] = l3b[0];
    for (int idx = tid; idx < 74 * 32; idx += 128) {
        int j = idx / 74, k = idx - j * 74;
        sW1[k * 32 + j] = l1W[idx];
    }
    for (int idx = tid; idx < 32 * 32; idx += 128) {
        int j = idx >> 5, k = idx & 31;
        sW2[k * 32 + j] = l2W[idx];
    }
    __syncthreads();

    // build X: [74][128]  (first 64 = relu(agg*dinv + cb) + state, last 10 = xg)
    for (int idx = tid; idx < 2048; idx += 128) {
        int r = idx >> 4, kq = (idx & 15) << 2;
        int row = base + r;
        float4 v = make_float4(0.f, 0.f, 0.f, 0.f);
        if (row < NN) {
            float di = g_dinv[row];
            float4 a = *(const float4*)&g_agg[row * 64 + kq];
            float4 s = *(const float4*)&state[row * 64 + kq];
            v.x = fmaxf(a.x * di + scb[kq + 0], 0.f) + s.x;
            v.y = fmaxf(a.y * di + scb[kq + 1], 0.f) + s.y;
            v.z = fmaxf(a.z * di + scb[kq + 2], 0.f) + s.z;
            v.w = fmaxf(a.w * di + scb[kq + 3], 0.f) + s.w;
        }
        sX[(kq + 0) * 132 + r] = v.x;
        sX[(kq + 1) * 132 + r] = v.y;
        sX[(kq + 2) * 132 + r] = v.z;
        sX[(kq + 3) * 132 + r] = v.w;
    }
    for (int idx = tid; idx < 128 * 10; idx += 128) {
        int r = idx / 10, k = idx - r * 10;
        int row = base + r;
        sX[(64 + k) * 132 + r] = (row < NN) ? g_xg[(row / ACTD) * 10 + k] : 0.f;
    }
    __syncthreads();

    int warp = tid >> 5, lane = tid & 31;
    int rg = lane >> 2, cg = lane & 3;
    int rowb = warp * 32 + rg * 4;
    int colb = cg * 8;

    // GEMM1: [128 x 74] @ W1[74 x 32]
    ull acc[4][4];
#pragma unroll
    for (int r = 0; r < 4; r++)
#pragma unroll
        for (int c = 0; c < 4; c++) acc[r][c] = 0ull;
#pragma unroll 2
    for (int k = 0; k < 74; k++) {
        float4 xv = *(const float4*)&sX[k * 132 + rowb];
        ull xp[4] = {pk2(xv.x, xv.x), pk2(xv.y, xv.y), pk2(xv.z, xv.z), pk2(xv.w, xv.w)};
        const ulonglong2* wp = (const ulonglong2*)&sW1[k * 32 + colb];
        ulonglong2 wa = wp[0], wb = wp[1];
#pragma unroll
        for (int r = 0; r < 4; r++) {
            fma2(acc[r][0], xp[r], wa.x);
            fma2(acc[r][1], xp[r], wa.y);
            fma2(acc[r][2], xp[r], wb.x);
            fma2(acc[r][3], xp[r], wb.y);
        }
    }
    {
        float hv[4][8];
#pragma unroll
        for (int r = 0; r < 4; r++)
#pragma unroll
            for (int cp = 0; cp < 4; cp++) {
                float2 v = up2(acc[r][cp]);
                int c = colb + cp * 2;
                hv[r][cp * 2] = leakyf(v.x + sb1[c]);
                hv[r][cp * 2 + 1] = leakyf(v.y + sb1[c + 1]);
            }
#pragma unroll
        for (int c = 0; c < 8; c++) {
            float4 f = make_float4(hv[0][c], hv[1][c], hv[2][c], hv[3][c]);
            *(float4*)&sH[(colb + c) * 132 + rowb] = f;
        }
    }
    __syncthreads();

    // GEMM2: [128 x 32] @ W2[32 x 32]
#pragma unroll
    for (int r = 0; r < 4; r++)
#pragma unroll
        for (int c = 0; c < 4; c++) acc[r][c] = 0ull;
#pragma unroll 4
    for (int k = 0; k < 32; k++) {
        float4 xv = *(const float4*)&sH[k * 132 + rowb];
        ull xp[4] = {pk2(xv.x, xv.x), pk2(xv.y, xv.y), pk2(xv.z, xv.z), pk2(xv.w, xv.w)};
        const ulonglong2* wp = (const ulonglong2*)&sW2[k * 32 + colb];
        ulonglong2 wa = wp[0], wb = wp[1];
#pragma unroll
        for (int r = 0; r < 4; r++) {
            fma2(acc[r][0], xp[r], wa.x);
            fma2(acc[r][1], xp[r], wa.y);
            fma2(acc[r][2], xp[r], wb.x);
            fma2(acc[r][3], xp[r], wb.y);
        }
    }

    float srow[4];
#pragma unroll
    for (int r = 0; r < 4; r++) {
        float s = 0.f;
#pragma unroll
        for (int cp = 0; cp < 4; cp++) {
            float2 v = up2(acc[r][cp]);
            int c = colb + cp * 2;
            float h0 = leakyf(v.x + sb2[c]);
            float h1 = leakyf(v.y + sb2[c + 1]);
            s += h0 * sw3[c] + h1 * sw3[c + 1];
        }
        srow[r] = s;
    }
#pragma unroll
    for (int r = 0; r < 4; r++) {
        srow[r] += __shfl_xor_sync(0xffffffffu, srow[r], 1);
        srow[r] += __shfl_xor_sync(0xffffffffu, srow[r], 2);
    }
    float lsum = 0.f;
    if (cg == 0) {
        float b3 = sb3[0];
#pragma unroll
        for (int r = 0; r < 4; r++) {
            int node = base + rowb + r;
            if (node < NN) {
                float conc = softplusf(srow[r] + b3);
                g_conc[node] = conc;
                lsum += conc;
            }
        }
    }
#pragma unroll
    for (int off = 16; off; off >>= 1) lsum += __shfl_xor_sync(0xffffffffu, lsum, off);
    if (lane == 0) atomicAdd(&g_sum, lsum);
}

// ---------------- finalize (normalize + regularize) ----------------
__global__ void k_final(float* __restrict__ out, int writeReg) {
    int b = blockIdx.x * 256 + threadIdx.x;
    if (b == 0 && writeReg) out[NN] = g_sum * (1.0f / (float)NN);
    if (b >= BB) return;
    float c[ACTD];
    float s = 0.f;
#pragma unroll
    for (int a = 0; a < ACTD; a++) {
        c[a] = g_conc[b * ACTD + a];
        s += c[a];
    }
    float inv = 1.f / (s + 1e-20f);
#pragma unroll
    for (int a = 0; a < ACTD; a++) out[b * ACTD + a] = c[a] * inv;
}

// ---------------- launch ----------------
extern "C" void kernel_launch(void* const* d_in, const int* in_sizes, int n_in,
                              void* d_out, int out_size) {
    const float* state = (const float*)d_in[0];
    const void*  eidx  = d_in[1];
    const float* convW = (const float*)d_in[2];
    const float* convb = (const float*)d_in[3];
    const float* gW1   = (const float*)d_in[4];
    const float* gb1   = (const float*)d_in[5];
    const float* gW2   = (const float*)d_in[6];
    const float* gb2   = (const float*)d_in[7];
    const float* l1W   = (const float*)d_in[8];
    const float* l1b   = (const float*)d_in[9];
    const float* l2W   = (const float*)d_in[10];
    const float* l2b   = (const float*)d_in[11];
    const float* l3W   = (const float*)d_in[12];
    const float* l3b   = (const float*)d_in[13];
    float* out = (float*)d_out;

    cudaFuncSetAttribute(k_conv, cudaFuncAttributeMaxDynamicSharedMemorySize, CONV_SMEM);
    cudaFuncSetAttribute(k_glob, cudaFuncAttributeMaxDynamicSharedMemorySize, GLOB_SMEM);
    cudaFuncSetAttribute(k_mlp,  cudaFuncAttributeMaxDynamicSharedMemorySize, MLP_SMEM);

    k_zero<<<(NN + 255) / 256, 256>>>(eidx);
    k_edges<<<(EE + 255) / 256, 256>>>(eidx);
    k_dinv<<<(NN + 255) / 256, 256>>>();
    k_conv<<<(NN + 127) / 128, 256, CONV_SMEM>>>(state, convW);
    k_scatter<<<(EE * 8 + 255) / 256, 256>>>();
    k_tw1<<<(KIN * GLB) / 256, 256>>>(gW1);
    k_glob<<<(BB + 63) / 64, 512, GLOB_SMEM>>>(state, gb1, gW2, gb2);
    k_mlp<<<(NN + 127) / 128, 128, MLP_SMEM>>>(state, convb, l1W, l1b, l2W, l2b, l3W, l3b);
    k_final<<<(BB + 255) / 256, 256>>>(out, out_size > NN ? 1 : 0);
}

// round 4
// speedup vs baseline: 1.3557x; 1.0521x over previous
#include <cuda_runtime.h>

#define NN   150000
#define EE   1200000
#define ACTD 6
#define BB   25000
#define GLB  256
#define GOUT 10
#define KIN  384
#define NSCAN_BLK 147   // ceil(NN/1024)

typedef unsigned long long ull;

// ---------------- static device scratch ----------------
__device__ __align__(16) float g_h2[NN * 64];    // (state @ convW^T) * dinv[i]
__device__ __align__(16) float g_agg[NN * 64];   // gathered aggregation (incl. self)
__device__ float g_dinv[NN];
__device__ int   g_cnt[NN];
__device__ int   g_off[NN + 1];
__device__ int   g_cur[NN];
__device__ int   g_csr[EE];
__device__ int   g_bsum[256];
__device__ int   g_boff[256];
__device__ __align__(8) int2 g_sd[EE];
__device__ int   g_is64;
__device__ float g_gW1t[KIN * GLB];              // gW1 transposed [k][j]
__device__ float g_xg[BB * GOUT];
__device__ float g_conc[NN];
__device__ float g_sum;

// ---------------- helpers ----------------
__device__ __forceinline__ float leakyf(float x) { return x > 0.f ? x : 0.01f * x; }
__device__ __forceinline__ float softplusf(float x) {
    return fmaxf(x, 0.f) + log1pf(expf(-fabsf(x)));
}
__device__ __forceinline__ ull pk2(float x, float y) {
    ull r;
    asm("mov.b64 %0, {%1, %2};" : "=l"(r) : "f"(x), "f"(y));
    return r;
}
__device__ __forceinline__ void fma2(ull& d, ull a, ull b) {
    asm("fma.rn.f32x2 %0, %1, %2, %3;" : "=l"(d) : "l"(a), "l"(b), "l"(d));
}
__device__ __forceinline__ float2 up2(ull v) {
    float lo, hi;
    asm("mov.b64 {%0, %1}, %2;" : "=f"(lo), "=f"(hi) : "l"(v));
    return make_float2(lo, hi);
}

// ---------------- setup kernels ----------------
__global__ void k_zero(const void* __restrict__ eidx) {
    int i = blockIdx.x * 256 + threadIdx.x;
    if (i < NN) g_cnt[i] = 0;
    if (i == 0) {
        g_sum = 0.f;
        const long long* p64 = (const long long*)eidx;
        int is64 = 1;
#pragma unroll
        for (int t = 0; t < 8; t++) {
            unsigned long long v = (unsigned long long)p64[t];
            if (v >= (unsigned long long)NN) is64 = 0;
        }
        g_is64 = is64;
    }
}

__global__ void k_edges(const void* __restrict__ eidx) {
    int e = blockIdx.x * 256 + threadIdx.x;
    if (e >= EE) return;
    int s, d;
    if (g_is64) {
        const long long* p64 = (const long long*)eidx;
        s = (int)p64[e];
        d = (int)p64[EE + e];
    } else {
        const int* p32 = (const int*)eidx;
        s = p32[e];
        d = p32[EE + e];
    }
    g_sd[e] = make_int2(s, d);
    atomicAdd(&g_cnt[d], 1);
}

__global__ void k_dinv() {
    int i = blockIdx.x * 256 + threadIdx.x;
    if (i < NN) g_dinv[i] = rsqrtf((float)g_cnt[i] + 1.0f);
}

// ---- CSR scan: block sums -> scan of block sums -> offsets ----
__global__ __launch_bounds__(1024) void k_bsum() {
    __shared__ int sred[32];
    int tid = threadIdx.x;
    int i = blockIdx.x * 1024 + tid;
    int v = (i < NN) ? g_cnt[i] : 0;
    int w = v;
#pragma unroll
    for (int off = 16; off; off >>= 1) w += __shfl_xor_sync(0xffffffffu, w, off);
    if ((tid & 31) == 0) sred[tid >> 5] = w;
    __syncthreads();
    if (tid < 32) {
        int x = sred[tid];
#pragma unroll
        for (int off = 16; off; off >>= 1) x += __shfl_xor_sync(0xffffffffu, x, off);
        if (tid == 0) g_bsum[blockIdx.x] = x;
    }
}

__global__ __launch_bounds__(256) void k_bscan() {
    __shared__ int s[256];
    int tid = threadIdx.x;
    int v = (tid < NSCAN_BLK) ? g_bsum[tid] : 0;
    s[tid] = v;
    __syncthreads();
#pragma unroll
    for (int off = 1; off < 256; off <<= 1) {
        int t = (tid >= off) ? s[tid - off] : 0;
        __syncthreads();
        s[tid] += t;
        __syncthreads();
    }
    g_boff[tid] = s[tid] - v;   // exclusive
    if (tid == 0) g_off[NN] = EE;
}

__global__ __launch_bounds__(1024) void k_off() {
    __shared__ int s[1024];
    int tid = threadIdx.x;
    int i = blockIdx.x * 1024 + tid;
    int v = (i < NN) ? g_cnt[i] : 0;
    s[tid] = v;
    __syncthreads();
#pragma unroll
    for (int off = 1; off < 1024; off <<= 1) {
        int t = (tid >= off) ? s[tid - off] : 0;
        __syncthreads();
        s[tid] += t;
        __syncthreads();
    }
    if (i < NN) {
        int excl = s[tid] - v + g_boff[blockIdx.x];
        g_off[i] = excl;
        g_cur[i] = excl;
    }
}

__global__ void k_fill() {
    int e = blockIdx.x * 256 + threadIdx.x;
    if (e >= EE) return;
    int2 sd = g_sd[e];
    int pos = atomicAdd(&g_cur[sd.y], 1);
    g_csr[pos] = sd.x;
}

__global__ void k_tw1(const float* __restrict__ gW1) {
    int idx = blockIdx.x * 256 + threadIdx.x;
    if (idx >= KIN * GLB) return;
    int k = idx / GLB, j = idx % GLB;
    g_gW1t[idx] = gW1[j * KIN + k];
}

// ---------------- k_conv ----------------
#define CONV_SX 0             // [64][132]
#define CONV_SW (64 * 132)    // [64][68]
#define CONV_SMEM ((64 * 132 + 64 * 68) * 4)
__global__ __launch_bounds__(256) void k_conv(const float* __restrict__ state,
                                              const float* __restrict__ convW) {
    extern __shared__ float sm[];
    float* sX = sm + CONV_SX;
    float* sW = sm + CONV_SW;
    int tid = threadIdx.x;
    int base = blockIdx.x * 128;

    for (int idx = tid; idx < 4096; idx += 256) {
        int o = idx >> 6, k = idx & 63;
        sW[k * 68 + o] = convW[idx];
    }
    for (int idx = tid; idx < 2048; idx += 256) {
        int r = idx >> 4, kq = (idx & 15) << 2;
        int row = base + r;
        float4 v = (row < NN) ? *(const float4*)&state[row * 64 + kq]
                              : make_float4(0.f, 0.f, 0.f, 0.f);
        sX[(kq + 0) * 132 + r] = v.x;
        sX[(kq + 1) * 132 + r] = v.y;
        sX[(kq + 2) * 132 + r] = v.z;
        sX[(kq + 3) * 132 + r] = v.w;
    }

    int warp = tid >> 5, lane = tid & 31;
    int rg = lane >> 2, cg = lane & 3;
    int rowb = (warp >> 1) * 32 + rg * 4;
    int colb = (warp & 1) * 32 + cg * 8;

    float di[4];
#pragma unroll
    for (int r = 0; r < 4; r++) {
        int row = base + rowb + r;
        di[r] = (row < NN) ? g_dinv[row] : 0.f;
    }
    __syncthreads();

    ull acc[4][4];
#pragma unroll
    for (int r = 0; r < 4; r++)
#pragma unroll
        for (int c = 0; c < 4; c++) acc[r][c] = 0ull;

#pragma unroll 16
    for (int k = 0; k < 64; k++) {
        float4 xv = *(const float4*)&sX[k * 132 + rowb];
        ull xp[4] = {pk2(xv.x, xv.x), pk2(xv.y, xv.y), pk2(xv.z, xv.z), pk2(xv.w, xv.w)};
        const ulonglong2* wp = (const ulonglong2*)&sW[k * 68 + colb];
        ulonglong2 wa = wp[0], wb = wp[1];
#pragma unroll
        for (int r = 0; r < 4; r++) {
            fma2(acc[r][0], xp[r], wa.x);
            fma2(acc[r][1], xp[r], wa.y);
            fma2(acc[r][2], xp[r], wb.x);
            fma2(acc[r][3], xp[r], wb.y);
        }
    }

#pragma unroll
    for (int r = 0; r < 4; r++) {
        int row = base + rowb + r;
        if (row >= NN) continue;
        float2 v0 = up2(acc[r][0]), v1 = up2(acc[r][1]);
        float2 v2 = up2(acc[r][2]), v3 = up2(acc[r][3]);
        *(float4*)&g_h2[row * 64 + colb] =
            make_float4(v0.x * di[r], v0.y * di[r], v1.x * di[r], v1.y * di[r]);
        *(float4*)&g_h2[row * 64 + colb + 4] =
            make_float4(v2.x * di[r], v2.y * di[r], v3.x * di[r], v3.y * di[r]);
    }
}

// ---------------- k_gather: 4 threads/node, 16 channels each ----------------
__global__ void k_gather() {
    int t = blockIdx.x * 256 + threadIdx.x;
    int node = t >> 2;
    if (node >= NN) return;
    int c = (t & 3) << 4;
    const float4* hb = (const float4*)&g_h2[node * 64 + c];
    float4 a0 = hb[0], a1 = hb[1], a2 = hb[2], a3 = hb[3];   // self term
    int j0 = g_off[node], j1 = g_off[node + 1];
    for (int j = j0; j < j1; j++) {
        int s = g_csr[j];
        const float4* p = (const float4*)&g_h2[s * 64 + c];
        float4 v0 = p[0], v1 = p[1], v2 = p[2], v3 = p[3];
        a0.x += v0.x; a0.y += v0.y; a0.z += v0.z; a0.w += v0.w;
        a1.x += v1.x; a1.y += v1.y; a1.z += v1.z; a1.w += v1.w;
        a2.x += v2.x; a2.y += v2.y; a2.z += v2.z; a2.w += v2.w;
        a3.x += v3.x; a3.y += v3.y; a3.z += v3.z; a3.w += v3.w;
    }
    float4* o = (float4*)&g_agg[node * 64 + c];
    o[0] = a0; o[1] = a1; o[2] = a2; o[3] = a3;
}

// ---------------- k_glob: 64 rows x 256 cols, 512 threads, dbuf W ----------------
#define GLOB_SIN 0                        // [384][68]
#define GLOB_SU  (384 * 68)               // union: 2 x W chunk [32][256] / H [64][260]
#define GLOB_SB1 (GLOB_SU + 64 * 260)     // [256]
#define GLOB_SMEM ((GLOB_SB1 + 256) * 4)
__global__ __launch_bounds__(512) void k_glob(const float* __restrict__ state,
                                              const float* __restrict__ gb1,
                                              const float* __restrict__ gW2,
                                              const float* __restrict__ gb2) {
    extern __shared__ float sm[];
    float* sIn = sm + GLOB_SIN;
    float* sU = sm + GLOB_SU;
    float* sb1 = sm + GLOB_SB1;
    int tid = threadIdx.x;
    int base = blockIdx.x * 64;

    for (int idx = tid; idx < 64 * KIN; idx += 512) {
        int r = idx / KIN, k = idx - r * KIN;
        int b = base + r;
        sIn[k * 68 + r] = (b < BB) ? state[b * KIN + k] : 0.f;
    }
    if (tid < 256) sb1[tid] = gb1[tid];

    int warp = tid >> 5, lane = tid & 31;
    int rg = lane >> 2, cg = lane & 3;
    int rowb = (warp >> 3) * 32 + rg * 4;
    int colb = (warp & 7) * 32 + cg * 8;

    ull acc[4][4];
#pragma unroll
    for (int r = 0; r < 4; r++)
#pragma unroll
        for (int c = 0; c < 4; c++) acc[r][c] = 0ull;

    // each thread stages 16 floats (4 float4) per 32x256 chunk
    float4 wreg[4];
#pragma unroll
    for (int q = 0; q < 4; q++)
        wreg[q] = *(const float4*)&g_gW1t[(tid * 4 + q * 2048)];

#pragma unroll 1
    for (int ch = 0; ch < 12; ch++) {
        float* buf = sU + (ch & 1) * 8192;
#pragma unroll
        for (int q = 0; q < 4; q++)
            *(float4*)&buf[tid * 4 + q * 2048] = wreg[q];
        __syncthreads();
        if (ch + 1 < 12) {
            const float* src = &g_gW1t[(ch + 1) * 8192];
#pragma unroll
            for (int q = 0; q < 4; q++)
                wreg[q] = *(const float4*)&src[tid * 4 + q * 2048];
        }
#pragma unroll 8
        for (int kk = 0; kk < 32; kk++) {
            float4 xv = *(const float4*)&sIn[(ch * 32 + kk) * 68 + rowb];
            ull xp[4] = {pk2(xv.x, xv.x), pk2(xv.y, xv.y), pk2(xv.z, xv.z), pk2(xv.w, xv.w)};
            const ulonglong2* wp = (const ulonglong2*)&buf[kk * 256 + colb];
            ulonglong2 wa = wp[0], wb = wp[1];
#pragma unroll
            for (int r = 0; r < 4; r++) {
                fma2(acc[r][0], xp[r], wa.x);
                fma2(acc[r][1], xp[r], wa.y);
                fma2(acc[r][2], xp[r], wb.x);
                fma2(acc[r][3], xp[r], wb.y);
            }
        }
        __syncthreads();
    }

    // write H = leaky(acc + b1) into sU [64][260]
#pragma unroll
    for (int r = 0; r < 4; r++) {
        int row = rowb + r;
#pragma unroll
        for (int cp = 0; cp < 4; cp++) {
            int c = colb + cp * 2;
            float2 v = up2(acc[r][cp]);
            float2 h;
            h.x = leakyf(v.x + sb1[c]);
            h.y = leakyf(v.y + sb1[c + 1]);
            *(float2*)&sU[row * 260 + c] = h;
        }
    }
    __syncthreads();

    for (int t = tid; t < 64 * GOUT; t += 512) {
        int r = t / GOUT, o = t - r * GOUT;
        float a = gb2[o];
        const float* hr = &sU[r * 260];
        const float* wr = &gW2[o * GLB];
#pragma unroll 8
        for (int j = 0; j < GLB; j++) a += hr[j] * wr[j];
        int b = base + r;
        if (b < BB) g_xg[b * GOUT + o] = leakyf(a);
    }
}

// ---------------- k_mlp ----------------
#define MLP_SX  0                   // [74][132]
#define MLP_SH  (74 * 132)          // [32][132]
#define MLP_SW1 (MLP_SH + 32 * 132) // [74][32]
#define MLP_SW2 (MLP_SW1 + 74 * 32) // [32][32]
#define MLP_SCB (MLP_SW2 + 32 * 32) // [64]
#define MLP_SB1 (MLP_SCB + 64)      // [32]
#define MLP_SB2 (MLP_SB1 + 32)      // [32]
#define MLP_SW3 (MLP_SB2 + 32)      // [32]
#define MLP_SB3 (MLP_SW3 + 32)      // [1]
#define MLP_SMEM ((MLP_SB3 + 4) * 4)
__global__ __launch_bounds__(128) void k_mlp(const float* __restrict__ state,
                                             const float* __restrict__ convb,
                                             const float* __restrict__ l1W,
                                             const float* __restrict__ l1b,
                                             const float* __restrict__ l2W,
                                             const float* __restrict__ l2b,
                                             const float* __restrict__ l3W,
                                             const float* __restrict__ l3b) {
    extern __shared__ float sm[];
    float* sX = sm + MLP_SX;
    float* sH = sm + MLP_SH;
    float* sW1 = sm + MLP_SW1;
    float* sW2 = sm + MLP_SW2;
    float* scb = sm + MLP_SCB;
    float* sb1 = sm + MLP_SB1;
    float* sb2 = sm + MLP_SB2;
    float* sw3 = sm + MLP_SW3;
    float* sb3 = sm + MLP_SB3;

    int tid = threadIdx.x;
    int base = blockIdx.x * 128;

    if (tid < 64) scb[tid] = convb[tid];
    if (tid < 32) {
        sb1[tid] = l1b[tid];
        sb2[tid] = l2b[tid];
        sw3[tid] = l3W[tid];
    }
    if (tid == 0) sb3[0] = l3b[0];
    for (int idx = tid; idx < 74 * 32; idx += 128) {
        int j = idx / 74, k = idx - j * 74;
        sW1[k * 32 + j] = l1W[idx];
    }
    for (int idx = tid; idx < 32 * 32; idx += 128) {
        int j = idx >> 5, k = idx & 31;
        sW2[k * 32 + j] = l2W[idx];
    }
    __syncthreads();

    for (int idx = tid; idx < 2048; idx += 128) {
        int r = idx >> 4, kq = (idx & 15) << 2;
        int row = base + r;
        float4 v = make_float4(0.f, 0.f, 0.f, 0.f);
        if (row < NN) {
            float di = g_dinv[row];
            float4 a = *(const float4*)&g_agg[row * 64 + kq];
            float4 s = *(const float4*)&state[row * 64 + kq];
            v.x = fmaxf(a.x * di + scb[kq + 0], 0.f) + s.x;
            v.y = fmaxf(a.y * di + scb[kq + 1], 0.f) + s.y;
            v.z = fmaxf(a.z * di + scb[kq + 2], 0.f) + s.z;
            v.w = fmaxf(a.w * di + scb[kq + 3], 0.f) + s.w;
        }
        sX[(kq + 0) * 132 + r] = v.x;
        sX[(kq + 1) * 132 + r] = v.y;
        sX[(kq + 2) * 132 + r] = v.z;
        sX[(kq + 3) * 132 + r] = v.w;
    }
    for (int idx = tid; idx < 128 * 10; idx += 128) {
        int r = idx / 10, k = idx - r * 10;
        int row = base + r;
        sX[(64 + k) * 132 + r] = (row < NN) ? g_xg[(row / ACTD) * 10 + k] : 0.f;
    }
    __syncthreads();

    int warp = tid >> 5, lane = tid & 31;
    int rg = lane >> 2, cg = lane & 3;
    int rowb = warp * 32 + rg * 4;
    int colb = cg * 8;

    ull acc[4][4];
#pragma unroll
    for (int r = 0; r < 4; r++)
#pragma unroll
        for (int c = 0; c < 4; c++) acc[r][c] = 0ull;
#pragma unroll 2
    for (int k = 0; k < 74; k++) {
        float4 xv = *(const float4*)&sX[k * 132 + rowb];
        ull xp[4] = {pk2(xv.x, xv.x), pk2(xv.y, xv.y), pk2(xv.z, xv.z), pk2(xv.w, xv.w)};
        const ulonglong2* wp = (const ulonglong2*)&sW1[k * 32 + colb];
        ulonglong2 wa = wp[0], wb = wp[1];
#pragma unroll
        for (int r = 0; r < 4; r++) {
            fma2(acc[r][0], xp[r], wa.x);
            fma2(acc[r][1], xp[r], wa.y);
            fma2(acc[r][2], xp[r], wb.x);
            fma2(acc[r][3], xp[r], wb.y);
        }
    }
    {
        float hv[4][8];
#pragma unroll
        for (int r = 0; r < 4; r++)
#pragma unroll
            for (int cp = 0; cp < 4; cp++) {
                float2 v = up2(acc[r][cp]);
                int c = colb + cp * 2;
                hv[r][cp * 2] = leakyf(v.x + sb1[c]);
                hv[r][cp * 2 + 1] = leakyf(v.y + sb1[c + 1]);
            }
#pragma unroll
        for (int c = 0; c < 8; c++) {
            float4 f = make_float4(hv[0][c], hv[1][c], hv[2][c], hv[3][c]);
            *(float4*)&sH[(colb + c) * 132 + rowb] = f;
        }
    }
    __syncthreads();

#pragma unroll
    for (int r = 0; r < 4; r++)
#pragma unroll
        for (int c = 0; c < 4; c++) acc[r][c] = 0ull;
#pragma unroll 4
    for (int k = 0; k < 32; k++) {
        float4 xv = *(const float4*)&sH[k * 132 + rowb];
        ull xp[4] = {pk2(xv.x, xv.x), pk2(xv.y, xv.y), pk2(xv.z, xv.z), pk2(xv.w, xv.w)};
        const ulonglong2* wp = (const ulonglong2*)&sW2[k * 32 + colb];
        ulonglong2 wa = wp[0], wb = wp[1];
#pragma unroll
        for (int r = 0; r < 4; r++) {
            fma2(acc[r][0], xp[r], wa.x);
            fma2(acc[r][1], xp[r], wa.y);
            fma2(acc[r][2], xp[r], wb.x);
            fma2(acc[r][3], xp[r], wb.y);
        }
    }

    float srow[4];
#pragma unroll
    for (int r = 0; r < 4; r++) {
        float s = 0.f;
#pragma unroll
        for (int cp = 0; cp < 4; cp++) {
            float2 v = up2(acc[r][cp]);
            int c = colb + cp * 2;
            float h0 = leakyf(v.x + sb2[c]);
            float h1 = leakyf(v.y + sb2[c + 1]);
            s += h0 * sw3[c] + h1 * sw3[c + 1];
        }
        srow[r] = s;
    }
#pragma unroll
    for (int r = 0; r < 4; r++) {
        srow[r] += __shfl_xor_sync(0xffffffffu, srow[r], 1);
        srow[r] += __shfl_xor_sync(0xffffffffu, srow[r], 2);
    }
    float lsum = 0.f;
    if (cg == 0) {
        float b3 = sb3[0];
#pragma unroll
        for (int r = 0; r < 4; r++) {
            int node = base + rowb + r;
            if (node < NN) {
                float conc = softplusf(srow[r] + b3);
                g_conc[node] = conc;
                lsum += conc;
            }
        }
    }
#pragma unroll
    for (int off = 16; off; off >>= 1) lsum += __shfl_xor_sync(0xffffffffu, lsum, off);
    if (lane == 0) atomicAdd(&g_sum, lsum);
}

// ---------------- finalize ----------------
__global__ void k_final(float* __restrict__ out, int writeReg) {
    int b = blockIdx.x * 256 + threadIdx.x;
    if (b == 0 && writeReg) out[NN] = g_sum * (1.0f / (float)NN);
    if (b >= BB) return;
    float c[ACTD];
    float s = 0.f;
#pragma unroll
    for (int a = 0; a < ACTD; a++) {
        c[a] = g_conc[b * ACTD + a];
        s += c[a];
    }
    float inv = 1.f / (s + 1e-20f);
#pragma unroll
    for (int a = 0; a < ACTD; a++) out[b * ACTD + a] = c[a] * inv;
}

// ---------------- launch ----------------
extern "C" void kernel_launch(void* const* d_in, const int* in_sizes, int n_in,
                              void* d_out, int out_size) {
    const float* state = (const float*)d_in[0];
    const void*  eidx  = d_in[1];
    const float* convW = (const float*)d_in[2];
    const float* convb = (const float*)d_in[3];
    const float* gW1   = (const float*)d_in[4];
    const float* gb1   = (const float*)d_in[5];
    const float* gW2   = (const float*)d_in[6];
    const float* gb2   = (const float*)d_in[7];
    const float* l1W   = (const float*)d_in[8];
    const float* l1b   = (const float*)d_in[9];
    const float* l2W   = (const float*)d_in[10];
    const float* l2b   = (const float*)d_in[11];
    const float* l3W   = (const float*)d_in[12];
    const float* l3b   = (const float*)d_in[13];
    float* out = (float*)d_out;

    cudaFuncSetAttribute(k_conv, cudaFuncAttributeMaxDynamicSharedMemorySize, CONV_SMEM);
    cudaFuncSetAttribute(k_glob, cudaFuncAttributeMaxDynamicSharedMemorySize, GLOB_SMEM);
    cudaFuncSetAttribute(k_mlp,  cudaFuncAttributeMaxDynamicSharedMemorySize, MLP_SMEM);

    k_zero<<<(NN + 255) / 256, 256>>>(eidx);
    k_edges<<<(EE + 255) / 256, 256>>>(eidx);
    k_dinv<<<(NN + 255) / 256, 256>>>();
    k_bsum<<<NSCAN_BLK, 1024>>>();
    k_bscan<<<1, 256>>>();
    k_off<<<NSCAN_BLK, 1024>>>();
    k_fill<<<(EE + 255) / 256, 256>>>();
    k_conv<<<(NN + 127) / 128, 256, CONV_SMEM>>>(state, convW);
    k_gather<<<(NN * 4 + 255) / 256, 256>>>();
    k_tw1<<<(KIN * GLB) / 256, 256>>>(gW1);
    k_glob<<<(BB + 63) / 64, 512, GLOB_SMEM>>>(state, gb1, gW2, gb2);
    k_mlp<<<(NN + 127) / 128, 128, MLP_SMEM>>>(state, convb, l1W, l1b, l2W, l2b, l3W, l3b);
    k_final<<<(BB + 255) / 256, 256>>>(out, out_size > NN ? 1 : 0);
}

// round 5
// speedup vs baseline: 1.3868x; 1.0229x over previous
#include <cuda_runtime.h>

#define NN   150000
#define EE   1200000
#define ACTD 6
#define BB   25000
#define GLB  256
#define GOUT 10
#define KIN  384
#define NSCAN_BLK 147   // ceil(NN/1024)

typedef unsigned long long ull;

// ---------------- static device scratch ----------------
__device__ __align__(16) float g_h2[NN * 64];    // (state @ convW^T) * dinv[i]
__device__ __align__(16) float g_agg[NN * 64];   // gathered aggregation (incl. self)
__device__ float g_dinv[NN];
__device__ int   g_cnt[NN];
__device__ int   g_off[NN + 1];
__device__ int   g_cur[NN];
__device__ int   g_csr[EE];
__device__ int   g_bsum[256];
__device__ int   g_boff[256];
__device__ __align__(8) int2 g_sd[EE];
__device__ int   g_is64;
__device__ float g_gW1t[KIN * GLB];              // gW1 transposed [k][j]
__device__ float g_xg[BB * GOUT];
__device__ float g_conc[NN];
__device__ float g_sum;

// ---------------- helpers ----------------
__device__ __forceinline__ float leakyf(float x) { return x > 0.f ? x : 0.01f * x; }
__device__ __forceinline__ float softplusf(float x) {
    return fmaxf(x, 0.f) + log1pf(expf(-fabsf(x)));
}
__device__ __forceinline__ ull pk2(float x, float y) {
    ull r;
    asm("mov.b64 %0, {%1, %2};" : "=l"(r) : "f"(x), "f"(y));
    return r;
}
__device__ __forceinline__ void fma2(ull& d, ull a, ull b) {
    asm("fma.rn.f32x2 %0, %1, %2, %3;" : "=l"(d) : "l"(a), "l"(b), "l"(d));
}
__device__ __forceinline__ float2 up2(ull v) {
    float lo, hi;
    asm("mov.b64 {%0, %1}, %2;" : "=f"(lo), "=f"(hi) : "l"(v));
    return make_float2(lo, hi);
}

// ---------------- setup kernels ----------------
__global__ void k_zero(const void* __restrict__ eidx) {
    int i = blockIdx.x * 256 + threadIdx.x;
    if (i < NN) g_cnt[i] = 0;
    if (i == 0) {
        g_sum = 0.f;
        const long long* p64 = (const long long*)eidx;
        int is64 = 1;
#pragma unroll
        for (int t = 0; t < 8; t++) {
            unsigned long long v = (unsigned long long)p64[t];
            if (v >= (unsigned long long)NN) is64 = 0;
        }
        g_is64 = is64;
    }
}

__global__ void k_edges(const void* __restrict__ eidx) {
    int e = blockIdx.x * 256 + threadIdx.x;
    if (e >= EE) return;
    int s, d;
    if (g_is64) {
        const long long* p64 = (const long long*)eidx;
        s = (int)p64[e];
        d = (int)p64[EE + e];
    } else {
        const int* p32 = (const int*)eidx;
        s = p32[e];
        d = p32[EE + e];
    }
    g_sd[e] = make_int2(s, d);
    atomicAdd(&g_cnt[d], 1);
}

__global__ void k_dinv() {
    int i = blockIdx.x * 256 + threadIdx.x;
    if (i < NN) g_dinv[i] = rsqrtf((float)g_cnt[i] + 1.0f);
}

// ---- CSR scan ----
__global__ __launch_bounds__(1024) void k_bsum() {
    __shared__ int sred[32];
    int tid = threadIdx.x;
    int i = blockIdx.x * 1024 + tid;
    int v = (i < NN) ? g_cnt[i] : 0;
    int w = v;
#pragma unroll
    for (int off = 16; off; off >>= 1) w += __shfl_xor_sync(0xffffffffu, w, off);
    if ((tid & 31) == 0) sred[tid >> 5] = w;
    __syncthreads();
    if (tid < 32) {
        int x = sred[tid];
#pragma unroll
        for (int off = 16; off; off >>= 1) x += __shfl_xor_sync(0xffffffffu, x, off);
        if (tid == 0) g_bsum[blockIdx.x] = x;
    }
}

__global__ __launch_bounds__(256) void k_bscan() {
    __shared__ int s[256];
    int tid = threadIdx.x;
    int v = (tid < NSCAN_BLK) ? g_bsum[tid] : 0;
    s[tid] = v;
    __syncthreads();
#pragma unroll
    for (int off = 1; off < 256; off <<= 1) {
        int t = (tid >= off) ? s[tid - off] : 0;
        __syncthreads();
        s[tid] += t;
        __syncthreads();
    }
    g_boff[tid] = s[tid] - v;   // exclusive
    if (tid == 0) g_off[NN] = EE;
}

__global__ __launch_bounds__(1024) void k_off() {
    __shared__ int s[1024];
    int tid = threadIdx.x;
    int i = blockIdx.x * 1024 + tid;
    int v = (i < NN) ? g_cnt[i] : 0;
    s[tid] = v;
    __syncthreads();
#pragma unroll
    for (int off = 1; off < 1024; off <<= 1) {
        int t = (tid >= off) ? s[tid - off] : 0;
        __syncthreads();
        s[tid] += t;
        __syncthreads();
    }
    if (i < NN) {
        int excl = s[tid] - v + g_boff[blockIdx.x];
        g_off[i] = excl;
        g_cur[i] = excl;
    }
}

__global__ void k_fill() {
    int e = blockIdx.x * 256 + threadIdx.x;
    if (e >= EE) return;
    int2 sd = g_sd[e];
    int pos = atomicAdd(&g_cur[sd.y], 1);
    g_csr[pos] = sd.x;
}

__global__ void k_tw1(const float* __restrict__ gW1) {
    int idx = blockIdx.x * 256 + threadIdx.x;
    if (idx >= KIN * GLB) return;
    int k = idx / GLB, j = idx % GLB;
    g_gW1t[idx] = gW1[j * KIN + k];
}

// ---------------- k_conv ----------------
#define CONV_SX 0             // [64][132]
#define CONV_SW (64 * 132)    // [64][68]
#define CONV_SMEM ((64 * 132 + 64 * 68) * 4)
__global__ __launch_bounds__(256) void k_conv(const float* __restrict__ state,
                                              const float* __restrict__ convW) {
    extern __shared__ float sm[];
    float* sX = sm + CONV_SX;
    float* sW = sm + CONV_SW;
    int tid = threadIdx.x;
    int base = blockIdx.x * 128;

    for (int idx = tid; idx < 4096; idx += 256) {
        int o = idx >> 6, k = idx & 63;
        sW[k * 68 + o] = convW[idx];
    }
    for (int idx = tid; idx < 2048; idx += 256) {
        int r = idx >> 4, kq = (idx & 15) << 2;
        int row = base + r;
        float4 v = (row < NN) ? *(const float4*)&state[row * 64 + kq]
                              : make_float4(0.f, 0.f, 0.f, 0.f);
        sX[(kq + 0) * 132 + r] = v.x;
        sX[(kq + 1) * 132 + r] = v.y;
        sX[(kq + 2) * 132 + r] = v.z;
        sX[(kq + 3) * 132 + r] = v.w;
    }

    int warp = tid >> 5, lane = tid & 31;
    int rg = lane >> 2, cg = lane & 3;
    int rowb = (warp >> 1) * 32 + rg * 4;
    int colb = (warp & 1) * 32 + cg * 8;

    float di[4];
#pragma unroll
    for (int r = 0; r < 4; r++) {
        int row = base + rowb + r;
        di[r] = (row < NN) ? g_dinv[row] : 0.f;
    }
    __syncthreads();

    ull acc[4][4];
#pragma unroll
    for (int r = 0; r < 4; r++)
#pragma unroll
        for (int c = 0; c < 4; c++) acc[r][c] = 0ull;

#pragma unroll 16
    for (int k = 0; k < 64; k++) {
        float4 xv = *(const float4*)&sX[k * 132 + rowb];
        ull xp[4] = {pk2(xv.x, xv.x), pk2(xv.y, xv.y), pk2(xv.z, xv.z), pk2(xv.w, xv.w)};
        const ulonglong2* wp = (const ulonglong2*)&sW[k * 68 + colb];
        ulonglong2 wa = wp[0], wb = wp[1];
#pragma unroll
        for (int r = 0; r < 4; r++) {
            fma2(acc[r][0], xp[r], wa.x);
            fma2(acc[r][1], xp[r], wa.y);
            fma2(acc[r][2], xp[r], wb.x);
            fma2(acc[r][3], xp[r], wb.y);
        }
    }

#pragma unroll
    for (int r = 0; r < 4; r++) {
        int row = base + rowb + r;
        if (row >= NN) continue;
        float2 v0 = up2(acc[r][0]), v1 = up2(acc[r][1]);
        float2 v2 = up2(acc[r][2]), v3 = up2(acc[r][3]);
        *(float4*)&g_h2[row * 64 + colb] =
            make_float4(v0.x * di[r], v0.y * di[r], v1.x * di[r], v1.y * di[r]);
        *(float4*)&g_h2[row * 64 + colb + 4] =
            make_float4(v2.x * di[r], v2.y * di[r], v3.x * di[r], v3.y * di[r]);
    }
}

// ---------------- k_gather: ONE WARP PER NODE, float2 per lane ----------------
// Every edge load is a single warp-coherent 256B row read (2 line-wavefronts).
__global__ __launch_bounds__(256) void k_gather() {
    int node = (blockIdx.x * 256 + threadIdx.x) >> 5;
    if (node >= NN) return;
    int lane = threadIdx.x & 31;
    int c = lane * 2;

    float2 acc = *(const float2*)&g_h2[node * 64 + c];   // self term
    int j0 = g_off[node], j1 = g_off[node + 1];
    int j = j0;
    for (; j + 3 < j1; j += 4) {
        int s0 = g_csr[j], s1 = g_csr[j + 1], s2 = g_csr[j + 2], s3 = g_csr[j + 3];
        float2 v0 = *(const float2*)&g_h2[s0 * 64 + c];
        float2 v1 = *(const float2*)&g_h2[s1 * 64 + c];
        float2 v2 = *(const float2*)&g_h2[s2 * 64 + c];
        float2 v3 = *(const float2*)&g_h2[s3 * 64 + c];
        acc.x += v0.x + v1.x + v2.x + v3.x;
        acc.y += v0.y + v1.y + v2.y + v3.y;
    }
    for (; j < j1; j++) {
        int s = g_csr[j];
        float2 v = *(const float2*)&g_h2[s * 64 + c];
        acc.x += v.x;
        acc.y += v.y;
    }
    *(float2*)&g_agg[node * 64 + c] = acc;
}

// ---------------- k_glob: 64 rows x 256 cols, 512 threads, dbuf W ----------------
#define GLOB_SIN 0                        // [384][68]
#define GLOB_SU  (384 * 68)               // union: 2 x W chunk [32][256] / H [64][260]
#define GLOB_SB1 (GLOB_SU + 64 * 260)     // [256]
#define GLOB_SMEM ((GLOB_SB1 + 256) * 4)
__global__ __launch_bounds__(512) void k_glob(const float* __restrict__ state,
                                              const float* __restrict__ gb1,
                                              const float* __restrict__ gW2,
                                              const float* __restrict__ gb2) {
    extern __shared__ float sm[];
    float* sIn = sm + GLOB_SIN;
    float* sU = sm + GLOB_SU;
    float* sb1 = sm + GLOB_SB1;
    int tid = threadIdx.x;
    int base = blockIdx.x * 64;

    for (int idx = tid; idx < 64 * KIN; idx += 512) {
        int r = idx / KIN, k = idx - r * KIN;
        int b = base + r;
        sIn[k * 68 + r] = (b < BB) ? state[b * KIN + k] : 0.f;
    }
    if (tid < 256) sb1[tid] = gb1[tid];

    int warp = tid >> 5, lane = tid & 31;
    int rg = lane >> 2, cg = lane & 3;
    int rowb = (warp >> 3) * 32 + rg * 4;
    int colb = (warp & 7) * 32 + cg * 8;

    ull acc[4][4];
#pragma unroll
    for (int r = 0; r < 4; r++)
#pragma unroll
        for (int c = 0; c < 4; c++) acc[r][c] = 0ull;

    float4 wreg[4];
#pragma unroll
    for (int q = 0; q < 4; q++)
        wreg[q] = *(const float4*)&g_gW1t[(tid * 4 + q * 2048)];

#pragma unroll 1
    for (int ch = 0; ch < 12; ch++) {
        float* buf = sU + (ch & 1) * 8192;
#pragma unroll
        for (int q = 0; q < 4; q++)
            *(float4*)&buf[tid * 4 + q * 2048] = wreg[q];
        __syncthreads();
        if (ch + 1 < 12) {
            const float* src = &g_gW1t[(ch + 1) * 8192];
#pragma unroll
            for (int q = 0; q < 4; q++)
                wreg[q] = *(const float4*)&src[tid * 4 + q * 2048];
        }
#pragma unroll 8
        for (int kk = 0; kk < 32; kk++) {
            float4 xv = *(const float4*)&sIn[(ch * 32 + kk) * 68 + rowb];
            ull xp[4] = {pk2(xv.x, xv.x), pk2(xv.y, xv.y), pk2(xv.z, xv.z), pk2(xv.w, xv.w)};
            const ulonglong2* wp = (const ulonglong2*)&buf[kk * 256 + colb];
            ulonglong2 wa = wp[0], wb = wp[1];
#pragma unroll
            for (int r = 0; r < 4; r++) {
                fma2(acc[r][0], xp[r], wa.x);
                fma2(acc[r][1], xp[r], wa.y);
                fma2(acc[r][2], xp[r], wb.x);
                fma2(acc[r][3], xp[r], wb.y);
            }
        }
        __syncthreads();
    }

#pragma unroll
    for (int r = 0; r < 4; r++) {
        int row = rowb + r;
#pragma unroll
        for (int cp = 0; cp < 4; cp++) {
            int c = colb + cp * 2;
            float2 v = up2(acc[r][cp]);
            float2 h;
            h.x = leakyf(v.x + sb1[c]);
            h.y = leakyf(v.y + sb1[c + 1]);
            *(float2*)&sU[row * 260 + c] = h;
        }
    }
    __syncthreads();

    for (int t = tid; t < 64 * GOUT; t += 512) {
        int r = t / GOUT, o = t - r * GOUT;
        float a = gb2[o];
        const float* hr = &sU[r * 260];
        const float* wr = &gW2[o * GLB];
#pragma unroll 8
        for (int j = 0; j < GLB; j++) a += hr[j] * wr[j];
        int b = base + r;
        if (b < BB) g_xg[b * GOUT + o] = leakyf(a);
    }
}

// ---------------- k_mlp ----------------
#define MLP_SX  0                   // [74][132]
#define MLP_SH  (74 * 132)          // [32][132]
#define MLP_SW1 (MLP_SH + 32 * 132) // [74][32]
#define MLP_SW2 (MLP_SW1 + 74 * 32) // [32][32]
#define MLP_SCB (MLP_SW2 + 32 * 32) // [64]
#define MLP_SB1 (MLP_SCB + 64)      // [32]
#define MLP_SB2 (MLP_SB1 + 32)      // [32]
#define MLP_SW3 (MLP_SB2 + 32)      // [32]
#define MLP_SB3 (MLP_SW3 + 32)      // [1]
#define MLP_SMEM ((MLP_SB3 + 4) * 4)
__global__ __launch_bounds__(128) void k_mlp(const float* __restrict__ state,
                                             const float* __restrict__ convb,
                                             const float* __restrict__ l1W,
                                             const float* __restrict__ l1b,
                                             const float* __restrict__ l2W,
                                             const float* __restrict__ l2b,
                                             const float* __restrict__ l3W,
                                             const float* __restrict__ l3b) {
    extern __shared__ float sm[];
    float* sX = sm + MLP_SX;
    float* sH = sm + MLP_SH;
    float* sW1 = sm + MLP_SW1;
    float* sW2 = sm + MLP_SW2;
    float* scb = sm + MLP_SCB;
    float* sb1 = sm + MLP_SB1;
    float* sb2 = sm + MLP_SB2;
    float* sw3 = sm + MLP_SW3;
    float* sb3 = sm + MLP_SB3;

    int tid = threadIdx.x;
    int base = blockIdx.x * 128;

    if (tid < 64) scb[tid] = convb[tid];
    if (tid < 32) {
        sb1[tid] = l1b[tid];
        sb2[tid] = l2b[tid];
        sw3[tid] = l3W[tid];
    }
    if (tid == 0) sb3[0] = l3b[0];
    for (int idx = tid; idx < 74 * 32; idx += 128) {
        int j = idx / 74, k = idx - j * 74;
        sW1[k * 32 + j] = l1W[idx];
    }
    for (int idx = tid; idx < 32 * 32; idx += 128) {
        int j = idx >> 5, k = idx & 31;
        sW2[k * 32 + j] = l2W[idx];
    }
    __syncthreads();

    for (int idx = tid; idx < 2048; idx += 128) {
        int r = idx >> 4, kq = (idx & 15) << 2;
        int row = base + r;
        float4 v = make_float4(0.f, 0.f, 0.f, 0.f);
        if (row < NN) {
            float di = g_dinv[row];
            float4 a = *(const float4*)&g_agg[row * 64 + kq];
            float4 s = *(const float4*)&state[row * 64 + kq];
            v.x = fmaxf(a.x * di + scb[kq + 0], 0.f) + s.x;
            v.y = fmaxf(a.y * di + scb[kq + 1], 0.f) + s.y;
            v.z = fmaxf(a.z * di + scb[kq + 2], 0.f) + s.z;
            v.w = fmaxf(a.w * di + scb[kq + 3], 0.f) + s.w;
        }
        sX[(kq + 0) * 132 + r] = v.x;
        sX[(kq + 1) * 132 + r] = v.y;
        sX[(kq + 2) * 132 + r] = v.z;
        sX[(kq + 3) * 132 + r] = v.w;
    }
    for (int idx = tid; idx < 128 * 10; idx += 128) {
        int r = idx / 10, k = idx - r * 10;
        int row = base + r;
        sX[(64 + k) * 132 + r] = (row < NN) ? g_xg[(row / ACTD) * 10 + k] : 0.f;
    }
    __syncthreads();

    int warp = tid >> 5, lane = tid & 31;
    int rg = lane >> 2, cg = lane & 3;
    int rowb = warp * 32 + rg * 4;
    int colb = cg * 8;

    ull acc[4][4];
#pragma unroll
    for (int r = 0; r < 4; r++)
#pragma unroll
        for (int c = 0; c < 4; c++) acc[r][c] = 0ull;
#pragma unroll 2
    for (int k = 0; k < 74; k++) {
        float4 xv = *(const float4*)&sX[k * 132 + rowb];
        ull xp[4] = {pk2(xv.x, xv.x), pk2(xv.y, xv.y), pk2(xv.z, xv.z), pk2(xv.w, xv.w)};
        const ulonglong2* wp = (const ulonglong2*)&sW1[k * 32 + colb];
        ulonglong2 wa = wp[0], wb = wp[1];
#pragma unroll
        for (int r = 0; r < 4; r++) {
            fma2(acc[r][0], xp[r], wa.x);
            fma2(acc[r][1], xp[r], wa.y);
            fma2(acc[r][2], xp[r], wb.x);
            fma2(acc[r][3], xp[r], wb.y);
        }
    }
    {
        float hv[4][8];
#pragma unroll
        for (int r = 0; r < 4; r++)
#pragma unroll
            for (int cp = 0; cp < 4; cp++) {
                float2 v = up2(acc[r][cp]);
                int c = colb + cp * 2;
                hv[r][cp * 2] = leakyf(v.x + sb1[c]);
                hv[r][cp * 2 + 1] = leakyf(v.y + sb1[c + 1]);
            }
#pragma unroll
        for (int c = 0; c < 8; c++) {
            float4 f = make_float4(hv[0][c], hv[1][c], hv[2][c], hv[3][c]);
            *(float4*)&sH[(colb + c) * 132 + rowb] = f;
        }
    }
    __syncthreads();

#pragma unroll
    for (int r = 0; r < 4; r++)
#pragma unroll
        for (int c = 0; c < 4; c++) acc[r][c] = 0ull;
#pragma unroll 4
    for (int k = 0; k < 32; k++) {
        float4 xv = *(const float4*)&sH[k * 132 + rowb];
        ull xp[4] = {pk2(xv.x, xv.x), pk2(xv.y, xv.y), pk2(xv.z, xv.z), pk2(xv.w, xv.w)};
        const ulonglong2* wp = (const ulonglong2*)&sW2[k * 32 + colb];
        ulonglong2 wa = wp[0], wb = wp[1];
#pragma unroll
        for (int r = 0; r < 4; r++) {
            fma2(acc[r][0], xp[r], wa.x);
            fma2(acc[r][1], xp[r], wa.y);
            fma2(acc[r][2], xp[r], wb.x);
            fma2(acc[r][3], xp[r], wb.y);
        }
    }

    float srow[4];
#pragma unroll
    for (int r = 0; r < 4; r++) {
        float s = 0.f;
#pragma unroll
        for (int cp = 0; cp < 4; cp++) {
            float2 v = up2(acc[r][cp]);
            int c = colb + cp * 2;
            float h0 = leakyf(v.x + sb2[c]);
            float h1 = leakyf(v.y + sb2[c + 1]);
            s += h0 * sw3[c] + h1 * sw3[c + 1];
        }
        srow[r] = s;
    }
#pragma unroll
    for (int r = 0; r < 4; r++) {
        srow[r] += __shfl_xor_sync(0xffffffffu, srow[r], 1);
        srow[r] += __shfl_xor_sync(0xffffffffu, srow[r], 2);
    }
    float lsum = 0.f;
    if (cg == 0) {
        float b3 = sb3[0];
#pragma unroll
        for (int r = 0; r < 4; r++) {
            int node = base + rowb + r;
            if (node < NN) {
                float conc = softplusf(srow[r] + b3);
                g_conc[node] = conc;
                lsum += conc;
            }
        }
    }
#pragma unroll
    for (int off = 16; off; off >>= 1) lsum += __shfl_xor_sync(0xffffffffu, lsum, off);
    if (lane == 0) atomicAdd(&g_sum, lsum);
}

// ---------------- finalize ----------------
__global__ void k_final(float* __restrict__ out, int writeReg) {
    int b = blockIdx.x * 256 + threadIdx.x;
    if (b == 0 && writeReg) out[NN] = g_sum * (1.0f / (float)NN);
    if (b >= BB) return;
    float c[ACTD];
    float s = 0.f;
#pragma unroll
    for (int a = 0; a < ACTD; a++) {
        c[a] = g_conc[b * ACTD + a];
        s += c[a];
    }
    float inv = 1.f / (s + 1e-20f);
#pragma unroll
    for (int a = 0; a < ACTD; a++) out[b * ACTD + a] = c[a] * inv;
}

// ---------------- launch ----------------
extern "C" void kernel_launch(void* const* d_in, const int* in_sizes, int n_in,
                              void* d_out, int out_size) {
    const float* state = (const float*)d_in[0];
    const void*  eidx  = d_in[1];
    const float* convW = (const float*)d_in[2];
    const float* convb = (const float*)d_in[3];
    const float* gW1   = (const float*)d_in[4];
    const float* gb1   = (const float*)d_in[5];
    const float* gW2   = (const float*)d_in[6];
    const float* gb2   = (const float*)d_in[7];
    const float* l1W   = (const float*)d_in[8];
    const float* l1b   = (const float*)d_in[9];
    const float* l2W   = (const float*)d_in[10];
    const float* l2b   = (const float*)d_in[11];
    const float* l3W   = (const float*)d_in[12];
    const float* l3b   = (const float*)d_in[13];
    float* out = (float*)d_out;

    cudaFuncSetAttribute(k_conv, cudaFuncAttributeMaxDynamicSharedMemorySize, CONV_SMEM);
    cudaFuncSetAttribute(k_glob, cudaFuncAttributeMaxDynamicSharedMemorySize, GLOB_SMEM);
    cudaFuncSetAttribute(k_mlp,  cudaFuncAttributeMaxDynamicSharedMemorySize, MLP_SMEM);

    k_zero<<<(NN + 255) / 256, 256>>>(eidx);
    k_edges<<<(EE + 255) / 256, 256>>>(eidx);
    k_dinv<<<(NN + 255) / 256, 256>>>();
    k_bsum<<<NSCAN_BLK, 1024>>>();
    k_bscan<<<1, 256>>>();
    k_off<<<NSCAN_BLK, 1024>>>();
    k_fill<<<(EE + 255) / 256, 256>>>();
    k_conv<<<(NN + 127) / 128, 256, CONV_SMEM>>>(state, convW);
    k_gather<<<(NN * 32 + 255) / 256, 256>>>();
    k_tw1<<<(KIN * GLB) / 256, 256>>>(gW1);
    k_glob<<<(BB + 63) / 64, 512, GLOB_SMEM>>>(state, gb1, gW2, gb2);
    k_mlp<<<(NN + 127) / 128, 128, MLP_SMEM>>>(state, convb, l1W, l1b, l2W, l2b, l3W, l3b);
    k_final<<<(BB + 255) / 256, 256>>>(out, out_size > NN ? 1 : 0);
}

// round 6
// speedup vs baseline: 1.4471x; 1.0435x over previous
#include <cuda_runtime.h>

#define NN   150000
#define EE   1200000
#define ACTD 6
#define BB   25000
#define GLB  256
#define GOUT 10
#define KIN  384
#define NSCAN_BLK 147   // ceil(NN/1024)

typedef unsigned long long ull;

// ---------------- static device scratch ----------------
__device__ __align__(16) float g_h2[NN * 64];    // (state @ convW^T) * dinv[i]
__device__ __align__(16) float g_agg[NN * 64];   // gathered aggregation (incl. self)
__device__ float g_dinv[NN];
__device__ int   g_cnt[NN];
__device__ int   g_off[NN + 1];
__device__ int   g_cur[NN];
__device__ int   g_csr[EE];
__device__ int   g_bsum[256];
__device__ int   g_boff[256];
__device__ __align__(8) int2 g_sd[EE];
__device__ int   g_is64;
__device__ float g_gW1t[KIN * GLB];              // gW1 transposed [k][j]
__device__ float g_xg[BB * GOUT];
__device__ float g_conc[NN];
__device__ float g_sum;

// ---------------- helpers ----------------
__device__ __forceinline__ float leakyf(float x) { return x > 0.f ? x : 0.01f * x; }
__device__ __forceinline__ float softplusf(float x) {
    return fmaxf(x, 0.f) + log1pf(expf(-fabsf(x)));
}
__device__ __forceinline__ ull pk2(float x, float y) {
    ull r;
    asm("mov.b64 %0, {%1, %2};" : "=l"(r) : "f"(x), "f"(y));
    return r;
}
__device__ __forceinline__ void fma2(ull& d, ull a, ull b) {
    asm("fma.rn.f32x2 %0, %1, %2, %3;" : "=l"(d) : "l"(a), "l"(b), "l"(d));
}
__device__ __forceinline__ float2 up2(ull v) {
    float lo, hi;
    asm("mov.b64 {%0, %1}, %2;" : "=f"(lo), "=f"(hi) : "l"(v));
    return make_float2(lo, hi);
}

// ---------------- setup kernels ----------------
__global__ void k_zero(const void* __restrict__ eidx) {
    int i = blockIdx.x * 256 + threadIdx.x;
    if (i < NN) g_cnt[i] = 0;
    if (i == 0) {
        g_sum = 0.f;
        const long long* p64 = (const long long*)eidx;
        int is64 = 1;
#pragma unroll
        for (int t = 0; t < 8; t++) {
            unsigned long long v = (unsigned long long)p64[t];
            if (v >= (unsigned long long)NN) is64 = 0;
        }
        g_is64 = is64;
    }
}

__global__ void k_edges(const void* __restrict__ eidx) {
    int e = blockIdx.x * 256 + threadIdx.x;
    if (e >= EE) return;
    int s, d;
    if (g_is64) {
        const long long* p64 = (const long long*)eidx;
        s = (int)p64[e];
        d = (int)p64[EE + e];
    } else {
        const int* p32 = (const int*)eidx;
        s = p32[e];
        d = p32[EE + e];
    }
    g_sd[e] = make_int2(s, d);
    atomicAdd(&g_cnt[d], 1);
}

__global__ void k_dinv() {
    int i = blockIdx.x * 256 + threadIdx.x;
    if (i < NN) g_dinv[i] = rsqrtf((float)g_cnt[i] + 1.0f);
}

// ---- CSR scan ----
__global__ __launch_bounds__(1024) void k_bsum() {
    __shared__ int sred[32];
    int tid = threadIdx.x;
    int i = blockIdx.x * 1024 + tid;
    int v = (i < NN) ? g_cnt[i] : 0;
    int w = v;
#pragma unroll
    for (int off = 16; off; off >>= 1) w += __shfl_xor_sync(0xffffffffu, w, off);
    if ((tid & 31) == 0) sred[tid >> 5] = w;
    __syncthreads();
    if (tid < 32) {
        int x = sred[tid];
#pragma unroll
        for (int off = 16; off; off >>= 1) x += __shfl_xor_sync(0xffffffffu, x, off);
        if (tid == 0) g_bsum[blockIdx.x] = x;
    }
}

__global__ __launch_bounds__(256) void k_bscan() {
    __shared__ int s[256];
    int tid = threadIdx.x;
    int v = (tid < NSCAN_BLK) ? g_bsum[tid] : 0;
    s[tid] = v;
    __syncthreads();
#pragma unroll
    for (int off = 1; off < 256; off <<= 1) {
        int t = (tid >= off) ? s[tid - off] : 0;
        __syncthreads();
        s[tid] += t;
        __syncthreads();
    }
    g_boff[tid] = s[tid] - v;   // exclusive
    if (tid == 0) g_off[NN] = EE;
}

__global__ __launch_bounds__(1024) void k_off() {
    __shared__ int s[1024];
    int tid = threadIdx.x;
    int i = blockIdx.x * 1024 + tid;
    int v = (i < NN) ? g_cnt[i] : 0;
    s[tid] = v;
    __syncthreads();
#pragma unroll
    for (int off = 1; off < 1024; off <<= 1) {
        int t = (tid >= off) ? s[tid - off] : 0;
        __syncthreads();
        s[tid] += t;
        __syncthreads();
    }
    if (i < NN) {
        int excl = s[tid] - v + g_boff[blockIdx.x];
        g_off[i] = excl;
        g_cur[i] = excl;
    }
}

__global__ void k_fill() {
    int e = blockIdx.x * 256 + threadIdx.x;
    if (e >= EE) return;
    int2 sd = g_sd[e];
    int pos = atomicAdd(&g_cur[sd.y], 1);
    g_csr[pos] = sd.x;
}

__global__ void k_tw1(const float* __restrict__ gW1) {
    int idx = blockIdx.x * 256 + threadIdx.x;
    if (idx >= KIN * GLB) return;
    int k = idx / GLB, j = idx % GLB;
    g_gW1t[idx] = gW1[j * KIN + k];
}

// ---------------- k_conv ----------------
#define CONV_SX 0             // [64][132]
#define CONV_SW (64 * 132)    // [64][68]
#define CONV_SMEM ((64 * 132 + 64 * 68) * 4)
__global__ __launch_bounds__(256) void k_conv(const float* __restrict__ state,
                                              const float* __restrict__ convW) {
    extern __shared__ float sm[];
    float* sX = sm + CONV_SX;
    float* sW = sm + CONV_SW;
    int tid = threadIdx.x;
    int base = blockIdx.x * 128;

    for (int idx = tid; idx < 4096; idx += 256) {
        int o = idx >> 6, k = idx & 63;
        sW[k * 68 + o] = convW[idx];
    }
    for (int idx = tid; idx < 2048; idx += 256) {
        int r = idx >> 4, kq = (idx & 15) << 2;
        int row = base + r;
        float4 v = (row < NN) ? *(const float4*)&state[row * 64 + kq]
                              : make_float4(0.f, 0.f, 0.f, 0.f);
        sX[(kq + 0) * 132 + r] = v.x;
        sX[(kq + 1) * 132 + r] = v.y;
        sX[(kq + 2) * 132 + r] = v.z;
        sX[(kq + 3) * 132 + r] = v.w;
    }

    int warp = tid >> 5, lane = tid & 31;
    int rg = lane >> 2, cg = lane & 3;
    int rowb = (warp >> 1) * 32 + rg * 4;
    int colb = (warp & 1) * 32 + cg * 8;

    float di[4];
#pragma unroll
    for (int r = 0; r < 4; r++) {
        int row = base + rowb + r;
        di[r] = (row < NN) ? g_dinv[row] : 0.f;
    }
    __syncthreads();

    ull acc[4][4];
#pragma unroll
    for (int r = 0; r < 4; r++)
#pragma unroll
        for (int c = 0; c < 4; c++) acc[r][c] = 0ull;

#pragma unroll 16
    for (int k = 0; k < 64; k++) {
        float4 xv = *(const float4*)&sX[k * 132 + rowb];
        ull xp[4] = {pk2(xv.x, xv.x), pk2(xv.y, xv.y), pk2(xv.z, xv.z), pk2(xv.w, xv.w)};
        const ulonglong2* wp = (const ulonglong2*)&sW[k * 68 + colb];
        ulonglong2 wa = wp[0], wb = wp[1];
#pragma unroll
        for (int r = 0; r < 4; r++) {
            fma2(acc[r][0], xp[r], wa.x);
            fma2(acc[r][1], xp[r], wa.y);
            fma2(acc[r][2], xp[r], wb.x);
            fma2(acc[r][3], xp[r], wb.y);
        }
    }

#pragma unroll
    for (int r = 0; r < 4; r++) {
        int row = base + rowb + r;
        if (row >= NN) continue;
        float2 v0 = up2(acc[r][0]), v1 = up2(acc[r][1]);
        float2 v2 = up2(acc[r][2]), v3 = up2(acc[r][3]);
        *(float4*)&g_h2[row * 64 + colb] =
            make_float4(v0.x * di[r], v0.y * di[r], v1.x * di[r], v1.y * di[r]);
        *(float4*)&g_h2[row * 64 + colb + 4] =
            make_float4(v2.x * di[r], v2.y * di[r], v3.x * di[r], v3.y * di[r]);
    }
}

// ---------------- k_gather: one warp per node, float2 per lane ----------------
__global__ __launch_bounds__(256) void k_gather() {
    int node = (blockIdx.x * 256 + threadIdx.x) >> 5;
    if (node >= NN) return;
    int lane = threadIdx.x & 31;
    int c = lane * 2;

    float2 acc = *(const float2*)&g_h2[node * 64 + c];   // self term
    int j0 = g_off[node], j1 = g_off[node + 1];
    int j = j0;
    for (; j + 3 < j1; j += 4) {
        int s0 = g_csr[j], s1 = g_csr[j + 1], s2 = g_csr[j + 2], s3 = g_csr[j + 3];
        float2 v0 = *(const float2*)&g_h2[s0 * 64 + c];
        float2 v1 = *(const float2*)&g_h2[s1 * 64 + c];
        float2 v2 = *(const float2*)&g_h2[s2 * 64 + c];
        float2 v3 = *(const float2*)&g_h2[s3 * 64 + c];
        acc.x += v0.x + v1.x + v2.x + v3.x;
        acc.y += v0.y + v1.y + v2.y + v3.y;
    }
    for (; j < j1; j++) {
        int s = g_csr[j];
        float2 v = *(const float2*)&g_h2[s * 64 + c];
        acc.x += v.x;
        acc.y += v.y;
    }
    *(float2*)&g_agg[node * 64 + c] = acc;
}

// ---------------- k_glob v2: 32 rows x 256 cols, 256 threads ----------------
// K streamed in 24 chunks of 16, double-buffered, ONE sync per chunk.
// smem ~89KB -> 2 blocks/SM. H overlays sIn after GEMM1.
#define GKC 16                              // K per chunk
#define GNC (KIN / GKC)                     // 24 chunks
#define GLOB_SIN 0                          // [384][36] = 13824 floats (H overlay [32][260])
#define GLOB_SW  (KIN * 36)                 // 2 x [16][256] = 8192 floats
#define GLOB_SB1 (GLOB_SW + 2 * GKC * GLB)  // [256]
#define GLOB_SMEM ((GLOB_SB1 + 256) * 4)
__global__ __launch_bounds__(256) void k_glob(const float* __restrict__ state,
                                              const float* __restrict__ gb1,
                                              const float* __restrict__ gW2,
                                              const float* __restrict__ gb2) {
    extern __shared__ float sm[];
    float* sIn = sm + GLOB_SIN;
    float* sW = sm + GLOB_SW;
    float* sb1 = sm + GLOB_SB1;
    int tid = threadIdx.x;
    int base = blockIdx.x * 32;

    // stage input rows [32][384] transposed -> sIn[k][r]
    for (int idx = tid; idx < 32 * KIN; idx += 256) {
        int r = idx / KIN, k = idx - r * KIN;
        int b = base + r;
        sIn[k * 36 + r] = (b < BB) ? state[b * KIN + k] : 0.f;
    }
    sb1[tid] = gb1[tid];

    // prologue: chunk 0 -> buf0 (direct), chunk 1 -> regs
    float4 wreg[4];
#pragma unroll
    for (int q = 0; q < 4; q++) {
        float4 v = *(const float4*)&g_gW1t[(tid + q * 256) * 4];
        *(float4*)&sW[(tid + q * 256) * 4] = v;
    }
#pragma unroll
    for (int q = 0; q < 4; q++)
        wreg[q] = *(const float4*)&g_gW1t[GKC * GLB + (tid + q * 256) * 4];
    __syncthreads();

    int warp = tid >> 5, lane = tid & 31;
    int rg = lane >> 2, cg = lane & 3;
    int rowb = rg * 4;
    int colb = warp * 32 + cg * 8;

    ull acc[4][4];
#pragma unroll
    for (int r = 0; r < 4; r++)
#pragma unroll
        for (int c = 0; c < 4; c++) acc[r][c] = 0ull;

#pragma unroll 1
    for (int ch = 0; ch < GNC; ch++) {
        const float* buf = sW + (ch & 1) * (GKC * GLB);
        // stage chunk ch+1 (held in regs) into the other buffer, prefetch ch+2
        if (ch + 1 < GNC) {
            float* nbuf = sW + ((ch + 1) & 1) * (GKC * GLB);
#pragma unroll
            for (int q = 0; q < 4; q++)
                *(float4*)&nbuf[(tid + q * 256) * 4] = wreg[q];
            if (ch + 2 < GNC) {
                const float* src = &g_gW1t[(ch + 2) * GKC * GLB];
#pragma unroll
                for (int q = 0; q < 4; q++)
                    wreg[q] = *(const float4*)&src[(tid + q * 256) * 4];
            }
        }
#pragma unroll
        for (int kk = 0; kk < GKC; kk++) {
            float4 xv = *(const float4*)&sIn[(ch * GKC + kk) * 36 + rowb];
            ull xp[4] = {pk2(xv.x, xv.x), pk2(xv.y, xv.y), pk2(xv.z, xv.z), pk2(xv.w, xv.w)};
            const ulonglong2* wp = (const ulonglong2*)&buf[kk * 256 + colb];
            ulonglong2 wa = wp[0], wb = wp[1];
#pragma unroll
            for (int r = 0; r < 4; r++) {
                fma2(acc[r][0], xp[r], wa.x);
                fma2(acc[r][1], xp[r], wa.y);
                fma2(acc[r][2], xp[r], wb.x);
                fma2(acc[r][3], xp[r], wb.y);
            }
        }
        __syncthreads();
    }

    // H = leaky(acc + b1) into sIn region [32][260]
#pragma unroll
    for (int r = 0; r < 4; r++) {
        int row = rowb + r;
#pragma unroll
        for (int cp = 0; cp < 4; cp++) {
            int c = colb + cp * 2;
            float2 v = up2(acc[r][cp]);
            float2 h;
            h.x = leakyf(v.x + sb1[c]);
            h.y = leakyf(v.y + sb1[c + 1]);
            *(float2*)&sIn[row * 260 + c] = h;
        }
    }
    __syncthreads();

    // layer 2: [32 x 256] @ gW2^T[256 x 10]
    for (int t = tid; t < 32 * GOUT; t += 256) {
        int r = t / GOUT, o = t - r * GOUT;
        float a = gb2[o];
        const float* hr = &sIn[r * 260];
        const float* wr = &gW2[o * GLB];
#pragma unroll 8
        for (int j = 0; j < GLB; j++) a += hr[j] * wr[j];
        int b = base + r;
        if (b < BB) g_xg[b * GOUT + o] = leakyf(a);
    }
}

// ---------------- k_mlp ----------------
#define MLP_SX  0                   // [74][132]
#define MLP_SH  (74 * 132)          // [32][132]
#define MLP_SW1 (MLP_SH + 32 * 132) // [74][32]
#define MLP_SW2 (MLP_SW1 + 74 * 32) // [32][32]
#define MLP_SCB (MLP_SW2 + 32 * 32) // [64]
#define MLP_SB1 (MLP_SCB + 64)      // [32]
#define MLP_SB2 (MLP_SB1 + 32)      // [32]
#define MLP_SW3 (MLP_SB2 + 32)      // [32]
#define MLP_SB3 (MLP_SW3 + 32)      // [1]
#define MLP_SMEM ((MLP_SB3 + 4) * 4)
__global__ __launch_bounds__(128) void k_mlp(const float* __restrict__ state,
                                             const float* __restrict__ convb,
                                             const float* __restrict__ l1W,
                                             const float* __restrict__ l1b,
                                             const float* __restrict__ l2W,
                                             const float* __restrict__ l2b,
                                             const float* __restrict__ l3W,
                                             const float* __restrict__ l3b) {
    extern __shared__ float sm[];
    float* sX = sm + MLP_SX;
    float* sH = sm + MLP_SH;
    float* sW1 = sm + MLP_SW1;
    float* sW2 = sm + MLP_SW2;
    float* scb = sm + MLP_SCB;
    float* sb1 = sm + MLP_SB1;
    float* sb2 = sm + MLP_SB2;
    float* sw3 = sm + MLP_SW3;
    float* sb3 = sm + MLP_SB3;

    int tid = threadIdx.x;
    int base = blockIdx.x * 128;

    if (tid < 64) scb[tid] = convb[tid];
    if (tid < 32) {
        sb1[tid] = l1b[tid];
        sb2[tid] = l2b[tid];
        sw3[tid] = l3W[tid];
    }
    if (tid == 0) sb3[0] = l3b[0];
    for (int idx = tid; idx < 74 * 32; idx += 128) {
        int j = idx / 74, k = idx - j * 74;
        sW1[k * 32 + j] = l1W[idx];
    }
    for (int idx = tid; idx < 32 * 32; idx += 128) {
        int j = idx >> 5, k = idx & 31;
        sW2[k * 32 + j] = l2W[idx];
    }
    __syncthreads();

    for (int idx = tid; idx < 2048; idx += 128) {
        int r = idx >> 4, kq = (idx & 15) << 2;
        int row = base + r;
        float4 v = make_float4(0.f, 0.f, 0.f, 0.f);
        if (row < NN) {
            float di = g_dinv[row];
            float4 a = *(const float4*)&g_agg[row * 64 + kq];
            float4 s = *(const float4*)&state[row * 64 + kq];
            v.x = fmaxf(a.x * di + scb[kq + 0], 0.f) + s.x;
            v.y = fmaxf(a.y * di + scb[kq + 1], 0.f) + s.y;
            v.z = fmaxf(a.z * di + scb[kq + 2], 0.f) + s.z;
            v.w = fmaxf(a.w * di + scb[kq + 3], 0.f) + s.w;
        }
        sX[(kq + 0) * 132 + r] = v.x;
        sX[(kq + 1) * 132 + r] = v.y;
        sX[(kq + 2) * 132 + r] = v.z;
        sX[(kq + 3) * 132 + r] = v.w;
    }
    for (int idx = tid; idx < 128 * 10; idx += 128) {
        int r = idx / 10, k = idx - r * 10;
        int row = base + r;
        sX[(64 + k) * 132 + r] = (row < NN) ? g_xg[(row / ACTD) * 10 + k] : 0.f;
    }
    __syncthreads();

    int warp = tid >> 5, lane = tid & 31;
    int rg = lane >> 2, cg = lane & 3;
    int rowb = warp * 32 + rg * 4;
    int colb = cg * 8;

    ull acc[4][4];
#pragma unroll
    for (int r = 0; r < 4; r++)
#pragma unroll
        for (int c = 0; c < 4; c++) acc[r][c] = 0ull;
#pragma unroll 2
    for (int k = 0; k < 74; k++) {
        float4 xv = *(const float4*)&sX[k * 132 + rowb];
        ull xp[4] = {pk2(xv.x, xv.x), pk2(xv.y, xv.y), pk2(xv.z, xv.z), pk2(xv.w, xv.w)};
        const ulonglong2* wp = (const ulonglong2*)&sW1[k * 32 + colb];
        ulonglong2 wa = wp[0], wb = wp[1];
#pragma unroll
        for (int r = 0; r < 4; r++) {
            fma2(acc[r][0], xp[r], wa.x);
            fma2(acc[r][1], xp[r], wa.y);
            fma2(acc[r][2], xp[r], wb.x);
            fma2(acc[r][3], xp[r], wb.y);
        }
    }
    {
        float hv[4][8];
#pragma unroll
        for (int r = 0; r < 4; r++)
#pragma unroll
            for (int cp = 0; cp < 4; cp++) {
                float2 v = up2(acc[r][cp]);
                int c = colb + cp * 2;
                hv[r][cp * 2] = leakyf(v.x + sb1[c]);
                hv[r][cp * 2 + 1] = leakyf(v.y + sb1[c + 1]);
            }
#pragma unroll
        for (int c = 0; c < 8; c++) {
            float4 f = make_float4(hv[0][c], hv[1][c], hv[2][c], hv[3][c]);
            *(float4*)&sH[(colb + c) * 132 + rowb] = f;
        }
    }
    __syncthreads();

#pragma unroll
    for (int r = 0; r < 4; r++)
#pragma unroll
        for (int c = 0; c < 4; c++) acc[r][c] = 0ull;
#pragma unroll 4
    for (int k = 0; k < 32; k++) {
        float4 xv = *(const float4*)&sH[k * 132 + rowb];
        ull xp[4] = {pk2(xv.x, xv.x), pk2(xv.y, xv.y), pk2(xv.z, xv.z), pk2(xv.w, xv.w)};
        const ulonglong2* wp = (const ulonglong2*)&sW2[k * 32 + colb];
        ulonglong2 wa = wp[0], wb = wp[1];
#pragma unroll
        for (int r = 0; r < 4; r++) {
            fma2(acc[r][0], xp[r], wa.x);
            fma2(acc[r][1], xp[r], wa.y);
            fma2(acc[r][2], xp[r], wb.x);
            fma2(acc[r][3], xp[r], wb.y);
        }
    }

    float srow[4];
#pragma unroll
    for (int r = 0; r < 4; r++) {
        float s = 0.f;
#pragma unroll
        for (int cp = 0; cp < 4; cp++) {
            float2 v = up2(acc[r][cp]);
            int c = colb + cp * 2;
            float h0 = leakyf(v.x + sb2[c]);
            float h1 = leakyf(v.y + sb2[c + 1]);
            s += h0 * sw3[c] + h1 * sw3[c + 1];
        }
        srow[r] = s;
    }
#pragma unroll
    for (int r = 0; r < 4; r++) {
        srow[r] += __shfl_xor_sync(0xffffffffu, srow[r], 1);
        srow[r] += __shfl_xor_sync(0xffffffffu, srow[r], 2);
    }
    float lsum = 0.f;
    if (cg == 0) {
        float b3 = sb3[0];
#pragma unroll
        for (int r = 0; r < 4; r++) {
            int node = base + rowb + r;
            if (node < NN) {
                float conc = softplusf(srow[r] + b3);
                g_conc[node] = conc;
                lsum += conc;
            }
        }
    }
#pragma unroll
    for (int off = 16; off; off >>= 1) lsum += __shfl_xor_sync(0xffffffffu, lsum, off);
    if (lane == 0) atomicAdd(&g_sum, lsum);
}

// ---------------- finalize ----------------
__global__ void k_final(float* __restrict__ out, int writeReg) {
    int b = blockIdx.x * 256 + threadIdx.x;
    if (b == 0 && writeReg) out[NN] = g_sum * (1.0f / (float)NN);
    if (b >= BB) return;
    float c[ACTD];
    float s = 0.f;
#pragma unroll
    for (int a = 0; a < ACTD; a++) {
        c[a] = g_conc[b * ACTD + a];
        s += c[a];
    }
    float inv = 1.f / (s + 1e-20f);
#pragma unroll
    for (int a = 0; a < ACTD; a++) out[b * ACTD + a] = c[a] * inv;
}

// ---------------- launch ----------------
extern "C" void kernel_launch(void* const* d_in, const int* in_sizes, int n_in,
                              void* d_out, int out_size) {
    const float* state = (const float*)d_in[0];
    const void*  eidx  = d_in[1];
    const float* convW = (const float*)d_in[2];
    const float* convb = (const float*)d_in[3];
    const float* gW1   = (const float*)d_in[4];
    const float* gb1   = (const float*)d_in[5];
    const float* gW2   = (const float*)d_in[6];
    const float* gb2   = (const float*)d_in[7];
    const float* l1W   = (const float*)d_in[8];
    const float* l1b   = (const float*)d_in[9];
    const float* l2W   = (const float*)d_in[10];
    const float* l2b   = (const float*)d_in[11];
    const float* l3W   = (const float*)d_in[12];
    const float* l3b   = (const float*)d_in[13];
    float* out = (float*)d_out;

    cudaFuncSetAttribute(k_conv, cudaFuncAttributeMaxDynamicSharedMemorySize, CONV_SMEM);
    cudaFuncSetAttribute(k_glob, cudaFuncAttributeMaxDynamicSharedMemorySize, GLOB_SMEM);
    cudaFuncSetAttribute(k_mlp,  cudaFuncAttributeMaxDynamicSharedMemorySize, MLP_SMEM);

    // order chosen so the 4th launch (ncu capture slot) is k_glob
    k_tw1<<<(KIN * GLB) / 256, 256>>>(gW1);
    k_zero<<<(NN + 255) / 256, 256>>>(eidx);
    k_edges<<<(EE + 255) / 256, 256>>>(eidx);
    k_glob<<<(BB + 31) / 32, 256, GLOB_SMEM>>>(state, gb1, gW2, gb2);
    k_dinv<<<(NN + 255) / 256, 256>>>();
    k_bsum<<<NSCAN_BLK, 1024>>>();
    k_bscan<<<1, 256>>>();
    k_off<<<NSCAN_BLK, 1024>>>();
    k_fill<<<(EE + 255) / 256, 256>>>();
    k_conv<<<(NN + 127) / 128, 256, CONV_SMEM>>>(state, convW);
    k_gather<<<(NN * 32 + 255) / 256, 256>>>();
    k_mlp<<<(NN + 127) / 128, 128, MLP_SMEM>>>(state, convb, l1W, l1b, l2W, l2b, l3W, l3b);
    k_final<<<(BB + 255) / 256, 256>>>(out, out_size > NN ? 1 : 0);
}